// round 4
// baseline (speedup 1.0000x reference)
#include <cuda_runtime.h>
#include <cuda_bf16.h>

// ---------------------------------------------------------------------------
// MultiGAT: 2-layer GAT on GB300.
//   L1: h1 = x@W1 [N,128]; per-head (8x16) attention; aggregate; +b1; ELU
//   L2: h2 = elu@W2 [N,64]; 1-head attention; aggregate; +b2; log_softmax
// Softmax max-shift omitted (mathematically identical ratio; values bounded).
// edge_index dtype (int32 vs int64) auto-detected on device.
// ---------------------------------------------------------------------------

#define N_NODES 50000
#define NE      800000
#define ET      850000   // NE + N_NODES self loops

// -------- scratch (device globals; allocation-free) --------
__device__ __align__(16) float g_h1  [N_NODES * 128];
__device__ __align__(16) float g_agg1[N_NODES * 128];
__device__ __align__(16) float g_h2  [N_NODES * 64];
__device__ float g_nas1[N_NODES * 8];
__device__ float g_nad1[N_NODES * 8];
__device__ float g_den1[N_NODES * 8];
__device__ float g_ex1 [ET * 8];
__device__ float g_nas2[N_NODES];
__device__ float g_nad2[N_NODES];
__device__ float g_den2[N_NODES];
__device__ float g_ex2 [ET];
__device__ int   g_src [ET];
__device__ int   g_dst [ET];
__device__ int   g_is64;

__device__ __forceinline__ float eluf(float v) {
    return v > 0.f ? v : expm1f(v);
}

__device__ __forceinline__ void red4(float4* p, float4 v) {
    asm volatile("red.global.add.v4.f32 [%0], {%1,%2,%3,%4};"
                 :: "l"(p), "f"(v.x), "f"(v.y), "f"(v.z), "f"(v.w)
                 : "memory");
}

// -------- dtype probe: int64 iff first 64 int64-reads are all valid indices --------
__global__ void detect_k(const void* __restrict__ ei) {
    if (threadIdx.x == 0 && blockIdx.x == 0) {
        const long long* p = (const long long*)ei;
        int ok = 1;
#pragma unroll 4
        for (int i = 0; i < 64; i++) {
            long long v = p[i];
            if (v < 0 || v >= N_NODES) ok = 0;
        }
        g_is64 = ok;
    }
}

// -------- decode edge list (+ self loops) into int32 src/dst --------
__global__ void decode_k(const void* __restrict__ ei) {
    int e = blockIdx.x * blockDim.x + threadIdx.x;
    if (e >= ET) return;
    int s, d;
    if (e < NE) {
        if (g_is64) {
            const long long* p = (const long long*)ei;
            s = (int)p[e];
            d = (int)p[NE + e];
        } else {
            const int* p = (const int*)ei;
            s = p[e];
            d = p[NE + e];
        }
    } else {
        s = d = e - NE;
    }
    g_src[e] = s;
    g_dst[e] = d;
}

// -------- zero init --------
__global__ void zero_bufs(float* __restrict__ out) {
    int t = blockIdx.x * blockDim.x + threadIdx.x;
    if (t < N_NODES * 128) g_agg1[t] = 0.f;
    if (t < N_NODES * 64)  out[t]    = 0.f;
    if (t < N_NODES * 8)   g_den1[t] = 0.f;
    if (t < N_NODES)       g_den2[t] = 0.f;
}

// -------- tiled SGEMM: C[M,BN] = A[M,128] @ B[128,BN], optional fused (A+bias)->ELU --------
template<int BN, int TN, bool FUSE>
__global__ void gemm128(const float* __restrict__ A, const float* __restrict__ B,
                        const float* __restrict__ bias, float* __restrict__ C) {
    constexpr int BM = 128, BK = 16, K = 128;
    __shared__ float As[BK][BM + 4];
    __shared__ float Bs[BK][BN];
    const int tid = threadIdx.x;          // 256 threads
    const int tx = tid & 15;              // 16 col groups
    const int ty = tid >> 4;              // 16 row groups
    const int rowBase = blockIdx.x * BM;

    float acc[8][TN];
#pragma unroll
    for (int i = 0; i < 8; i++)
#pragma unroll
        for (int j = 0; j < TN; j++) acc[i][j] = 0.f;

    for (int kt = 0; kt < K; kt += BK) {
        // A tile (transposed into smem): 128 rows x 16 k
        {
            const int r  = tid >> 1;
            const int kg = (tid & 1) * 4;
#pragma unroll
            for (int rep = 0; rep < 2; rep++) {
                const int kk = kg + rep * 8;
                const int row = rowBase + r;
                float4 v = make_float4(0.f, 0.f, 0.f, 0.f);
                if (row < N_NODES)
                    v = *(const float4*)&A[row * K + kt + kk];
                if (FUSE) {
                    v.x = eluf(v.x + bias[kt + kk + 0]);
                    v.y = eluf(v.y + bias[kt + kk + 1]);
                    v.z = eluf(v.z + bias[kt + kk + 2]);
                    v.w = eluf(v.w + bias[kt + kk + 3]);
                }
                As[kk + 0][r] = v.x;
                As[kk + 1][r] = v.y;
                As[kk + 2][r] = v.z;
                As[kk + 3][r] = v.w;
            }
        }
        // B tile: 16 x BN contiguous
        {
            constexpr int TOT4 = BK * BN / 4;
            const float4* src4 = (const float4*)&B[kt * BN];
            float4* dst4 = (float4*)&Bs[0][0];
#pragma unroll
            for (int i = tid; i < TOT4; i += 256) dst4[i] = src4[i];
        }
        __syncthreads();
#pragma unroll
        for (int kk = 0; kk < BK; kk++) {
            float a[8], b[TN];
            float4 a0 = *(const float4*)&As[kk][ty * 8];
            float4 a1 = *(const float4*)&As[kk][ty * 8 + 4];
            a[0]=a0.x; a[1]=a0.y; a[2]=a0.z; a[3]=a0.w;
            a[4]=a1.x; a[5]=a1.y; a[6]=a1.z; a[7]=a1.w;
            float4 b0 = *(const float4*)&Bs[kk][tx * TN];
            b[0]=b0.x; b[1]=b0.y; b[2]=b0.z; b[3]=b0.w;
            if (TN == 8) {
                float4 b1 = *(const float4*)&Bs[kk][tx * TN + 4];
                b[4]=b1.x; b[5]=b1.y; b[6]=b1.z; b[7]=b1.w;
            }
#pragma unroll
            for (int i = 0; i < 8; i++)
#pragma unroll
                for (int j = 0; j < TN; j++) acc[i][j] += a[i] * b[j];
        }
        __syncthreads();
    }
#pragma unroll
    for (int i = 0; i < 8; i++) {
        const int row = rowBase + ty * 8 + i;
        if (row < N_NODES) {
#pragma unroll
            for (int j = 0; j < TN; j += 4)
                *(float4*)&C[row * BN + tx * TN + j] =
                    make_float4(acc[i][j], acc[i][j+1], acc[i][j+2], acc[i][j+3]);
        }
    }
}

// -------- per-node attention logits, layer 1: thread per (node, head) --------
__global__ void alpha1_k(const float* __restrict__ as1, const float* __restrict__ ad1) {
    int t = blockIdx.x * blockDim.x + threadIdx.x;
    if (t >= N_NODES * 8) return;
    const int n = t >> 3, h = t & 7;
    const float4* hp = (const float4*)g_h1 + n * 32 + h * 4;
    const float4* ap = (const float4*)as1 + h * 4;
    const float4* dp = (const float4*)ad1 + h * 4;
    float s = 0.f, d = 0.f;
#pragma unroll
    for (int i = 0; i < 4; i++) {
        float4 hv = hp[i], av = ap[i], dv = dp[i];
        s += hv.x * av.x + hv.y * av.y + hv.z * av.z + hv.w * av.w;
        d += hv.x * dv.x + hv.y * dv.y + hv.z * dv.z + hv.w * dv.w;
    }
    g_nas1[t] = s;
    g_nad1[t] = d;
}

// -------- layer-1 edge pass A: exp(leakyrelu) + denom accumulation --------
__global__ void edgeA1() {
    int t = blockIdx.x * blockDim.x + threadIdx.x;
    if (t >= ET * 8) return;
    const int e = t >> 3, h = t & 7;
    const int src = g_src[e], dst = g_dst[e];
    float v = g_nas1[src * 8 + h] + g_nad1[dst * 8 + h];
    v = v > 0.f ? v : 0.2f * v;
    const float ev = expf(v);
    g_ex1[e * 8 + h] = ev;
    atomicAdd(&g_den1[dst * 8 + h], ev);
}

// -------- layer-1 edge pass B: scatter h1[src]*alpha into agg1 (thread per float4) --------
__global__ void edgeB1() {
    int t = blockIdx.x * blockDim.x + threadIdx.x;
    if (t >= ET * 32) return;
    const int e = t >> 5, q = t & 31, h = q >> 2;
    const int src = g_src[e], dst = g_dst[e];
    const float a = g_ex1[e * 8 + h] / (g_den1[dst * 8 + h] + 1e-16f);
    float4 hv = ((const float4*)g_h1)[src * 32 + q];
    red4(&((float4*)g_agg1)[dst * 32 + q],
         make_float4(hv.x * a, hv.y * a, hv.z * a, hv.w * a));
}

// -------- per-node attention logits, layer 2: thread per node --------
__global__ void alpha2_k(const float* __restrict__ as2, const float* __restrict__ ad2) {
    int n = blockIdx.x * blockDim.x + threadIdx.x;
    if (n >= N_NODES) return;
    const float4* hp = (const float4*)g_h2 + n * 16;
    const float4* ap = (const float4*)as2;
    const float4* dp = (const float4*)ad2;
    float s = 0.f, d = 0.f;
#pragma unroll
    for (int i = 0; i < 16; i++) {
        float4 hv = hp[i], av = ap[i], dv = dp[i];
        s += hv.x * av.x + hv.y * av.y + hv.z * av.z + hv.w * av.w;
        d += hv.x * dv.x + hv.y * dv.y + hv.z * dv.z + hv.w * dv.w;
    }
    g_nas2[n] = s;
    g_nad2[n] = d;
}

// -------- layer-2 edge pass A --------
__global__ void edgeA2() {
    int e = blockIdx.x * blockDim.x + threadIdx.x;
    if (e >= ET) return;
    const int src = g_src[e], dst = g_dst[e];
    float v = g_nas2[src] + g_nad2[dst];
    v = v > 0.f ? v : 0.2f * v;
    const float ev = expf(v);
    g_ex2[e] = ev;
    atomicAdd(&g_den2[dst], ev);
}

// -------- layer-2 edge pass B: scatter into d_out (thread per float4) --------
__global__ void edgeB2(float* __restrict__ out) {
    int t = blockIdx.x * blockDim.x + threadIdx.x;
    if (t >= ET * 16) return;
    const int e = t >> 4, q = t & 15;
    const int src = g_src[e], dst = g_dst[e];
    const float a = g_ex2[e] / (g_den2[dst] + 1e-16f);
    float4 hv = ((const float4*)g_h2)[src * 16 + q];
    red4(&((float4*)out)[dst * 16 + q],
         make_float4(hv.x * a, hv.y * a, hv.z * a, hv.w * a));
}

// -------- +b2, log_softmax over 64 cols, in place; warp per node --------
__global__ void logsoftmax_k(float* __restrict__ out, const float* __restrict__ b2) {
    const int g = blockIdx.x * blockDim.x + threadIdx.x;
    const int node = g >> 5, lane = g & 31;
    if (node >= N_NODES) return;
    float* row = out + node * 64;
    float v0 = row[lane]      + b2[lane];
    float v1 = row[lane + 32] + b2[lane + 32];
    float mx = fmaxf(v0, v1);
#pragma unroll
    for (int o = 16; o > 0; o >>= 1)
        mx = fmaxf(mx, __shfl_xor_sync(0xFFFFFFFFu, mx, o));
    float s = expf(v0 - mx) + expf(v1 - mx);
#pragma unroll
    for (int o = 16; o > 0; o >>= 1)
        s += __shfl_xor_sync(0xFFFFFFFFu, s, o);
    const float lse = logf(s) + mx;
    row[lane]      = v0 - lse;
    row[lane + 32] = v1 - lse;
}

extern "C" void kernel_launch(void* const* d_in, const int* in_sizes, int n_in,
                              void* d_out, int out_size) {
    const float* x   = (const float*)d_in[0];
    const void*  ei  = d_in[1];                 // int32 or int64, auto-detected
    const float* W1  = (const float*)d_in[2];
    const float* as1 = (const float*)d_in[3];
    const float* ad1 = (const float*)d_in[4];
    const float* b1  = (const float*)d_in[5];
    const float* W2  = (const float*)d_in[6];
    const float* as2 = (const float*)d_in[7];
    const float* ad2 = (const float*)d_in[8];
    const float* b2  = (const float*)d_in[9];
    float* out = (float*)d_out;

    void *p_h1, *p_agg1, *p_h2;
    cudaGetSymbolAddress(&p_h1,   g_h1);
    cudaGetSymbolAddress(&p_agg1, g_agg1);
    cudaGetSymbolAddress(&p_h2,   g_h2);

    const int gemm_blocks = (N_NODES + 127) / 128;   // 391

    detect_k<<<1, 32>>>(ei);
    decode_k<<<(ET + 255) / 256, 256>>>(ei);
    zero_bufs<<<(N_NODES * 128 + 255) / 256, 256>>>(out);
    gemm128<128, 8, false><<<gemm_blocks, 256>>>(x, W1, nullptr, (float*)p_h1);
    alpha1_k<<<(N_NODES * 8 + 255) / 256, 256>>>(as1, ad1);
    edgeA1<<<(ET * 8 + 255) / 256, 256>>>();
    edgeB1<<<(ET * 32 + 255) / 256, 256>>>();
    gemm128<64, 4, true><<<gemm_blocks, 256>>>((const float*)p_agg1, W2, b1, (float*)p_h2);
    alpha2_k<<<(N_NODES + 255) / 256, 256>>>(as2, ad2);
    edgeA2<<<(ET + 255) / 256, 256>>>();
    edgeB2<<<(ET * 16 + 255) / 256, 256>>>(out);
    logsoftmax_k<<<(N_NODES * 32 + 255) / 256, 256>>>(out, b2);
}

// round 5
// speedup vs baseline: 1.0353x; 1.0353x over previous
#include <cuda_runtime.h>
#include <cuda_bf16.h>

// ---------------------------------------------------------------------------
// MultiGAT: 2-layer GAT on GB300, CSR gather-aggregate formulation (no float
// atomics). Softmax max-shift omitted (mathematically identical ratio).
// edge_index dtype (int32 vs int64) auto-detected on device.
// ---------------------------------------------------------------------------

#define N_NODES 50000
#define NE      800000
#define ET      850000   // NE + N_NODES self loops

// -------- scratch (device globals; allocation-free) --------
__device__ __align__(16) float g_h1  [N_NODES * 128];
__device__ __align__(16) float g_agg1[N_NODES * 128];
__device__ __align__(16) float g_h2  [N_NODES * 64];
__device__ float g_nas1[N_NODES * 8];
__device__ float g_nad1[N_NODES * 8];
__device__ float g_nas2[N_NODES];
__device__ float g_nad2[N_NODES];
__device__ int   g_src [ET];
__device__ int   g_dst [ET];
__device__ int   g_esrc[ET];            // CSR: src per slot, sorted by dst
__device__ int   g_rowptr[N_NODES + 1];
__device__ int   g_woff[N_NODES];
__device__ int   g_cnt [N_NODES];
__device__ int   g_is64;

__device__ __forceinline__ float eluf(float v) {
    return v > 0.f ? v : expm1f(v);
}

// -------- dtype probe: int64 iff first 64 int64-reads are all valid indices --------
__global__ void detect_k(const void* __restrict__ ei) {
    if (threadIdx.x == 0 && blockIdx.x == 0) {
        const long long* p = (const long long*)ei;
        int ok = 1;
#pragma unroll 4
        for (int i = 0; i < 64; i++) {
            long long v = p[i];
            if (v < 0 || v >= N_NODES) ok = 0;
        }
        g_is64 = ok;
    }
}

__global__ void zerocnt_k() {
    int t = blockIdx.x * blockDim.x + threadIdx.x;
    if (t < N_NODES) g_cnt[t] = 0;
}

// -------- decode edge list (+ self loops) into int32 src/dst + dst histogram ---
__global__ void decode_hist_k(const void* __restrict__ ei) {
    int e = blockIdx.x * blockDim.x + threadIdx.x;
    if (e >= ET) return;
    int s, d;
    if (e < NE) {
        if (g_is64) {
            const long long* p = (const long long*)ei;
            s = (int)p[e];
            d = (int)p[NE + e];
        } else {
            const int* p = (const int*)ei;
            s = p[e];
            d = p[NE + e];
        }
    } else {
        s = d = e - NE;
    }
    g_src[e] = s;
    g_dst[e] = d;
    atomicAdd(&g_cnt[d], 1);
}

// -------- single-block exclusive scan over g_cnt -> g_rowptr, g_woff --------
__global__ void scan_k() {
    __shared__ int sums[1024];
    const int t = threadIdx.x;
    const int C = (N_NODES + 1023) / 1024;   // 49
    const int lo = t * C;
    const int hi = min(lo + C, N_NODES);
    int s = 0;
    for (int i = lo; i < hi; i++) s += g_cnt[i];
    sums[t] = s;
    __syncthreads();
    if (t == 0) {
        int run = 0;
        for (int i = 0; i < 1024; i++) { int v = sums[i]; sums[i] = run; run += v; }
        g_rowptr[N_NODES] = run;
    }
    __syncthreads();
    int p = sums[t];
    for (int i = lo; i < hi; i++) {
        g_rowptr[i] = p;
        g_woff[i] = p;
        p += g_cnt[i];
    }
}

// -------- scatter edges into CSR slots --------
__global__ void scatter_k() {
    int e = blockIdx.x * blockDim.x + threadIdx.x;
    if (e >= ET) return;
    int slot = atomicAdd(&g_woff[g_dst[e]], 1);
    g_esrc[slot] = g_src[e];
}

// -------- tiled SGEMM: C[M,BN] = A[M,128] @ B[128,BN], 512 thr, 4xTN tiles ----
template<int BN, int TN, bool FUSE>
__global__ __launch_bounds__(512)
void gemm128(const float* __restrict__ A, const float* __restrict__ B,
             const float* __restrict__ bias, float* __restrict__ C) {
    constexpr int BM = 128, BK = 16, K = 128;
    __shared__ float As[BK][BM + 4];
    __shared__ float Bs[BK][BN];
    const int tid = threadIdx.x;          // 512 threads
    const int tx = tid & 15;              // 16 col groups * TN = BN
    const int ty = tid >> 4;              // 32 row groups * 4 = 128
    const int rowBase = blockIdx.x * BM;

    float acc[4][TN];
#pragma unroll
    for (int i = 0; i < 4; i++)
#pragma unroll
        for (int j = 0; j < TN; j++) acc[i][j] = 0.f;

    for (int kt = 0; kt < K; kt += BK) {
        // A tile (transposed into smem): one float4 per thread
        {
            const int r  = tid >> 2;              // 0..127
            const int kg = (tid & 3) * 4;         // 0,4,8,12
            const int row = rowBase + r;
            float4 v = make_float4(0.f, 0.f, 0.f, 0.f);
            if (row < N_NODES)
                v = *(const float4*)&A[row * K + kt + kg];
            if (FUSE) {
                v.x = eluf(v.x + bias[kt + kg + 0]);
                v.y = eluf(v.y + bias[kt + kg + 1]);
                v.z = eluf(v.z + bias[kt + kg + 2]);
                v.w = eluf(v.w + bias[kt + kg + 3]);
            }
            As[kg + 0][r] = v.x;
            As[kg + 1][r] = v.y;
            As[kg + 2][r] = v.z;
            As[kg + 3][r] = v.w;
        }
        // B tile: 16 x BN contiguous
        {
            constexpr int TOT4 = BK * BN / 4;
            const float4* src4 = (const float4*)&B[kt * BN];
            float4* dst4 = (float4*)&Bs[0][0];
#pragma unroll
            for (int i = tid; i < TOT4; i += 512) dst4[i] = src4[i];
        }
        __syncthreads();
#pragma unroll
        for (int kk = 0; kk < BK; kk++) {
            float a[4], b[TN];
            float4 a0 = *(const float4*)&As[kk][ty * 4];
            a[0]=a0.x; a[1]=a0.y; a[2]=a0.z; a[3]=a0.w;
            float4 b0 = *(const float4*)&Bs[kk][tx * TN];
            b[0]=b0.x; b[1]=b0.y; b[2]=b0.z; b[3]=b0.w;
            if (TN == 8) {
                float4 b1 = *(const float4*)&Bs[kk][tx * TN + 4];
                b[4]=b1.x; b[5]=b1.y; b[6]=b1.z; b[7]=b1.w;
            }
#pragma unroll
            for (int i = 0; i < 4; i++)
#pragma unroll
                for (int j = 0; j < TN; j++) acc[i][j] += a[i] * b[j];
        }
        __syncthreads();
    }
#pragma unroll
    for (int i = 0; i < 4; i++) {
        const int row = rowBase + ty * 4 + i;
        if (row < N_NODES) {
#pragma unroll
            for (int j = 0; j < TN; j += 4)
                *(float4*)&C[row * BN + tx * TN + j] =
                    make_float4(acc[i][j], acc[i][j+1], acc[i][j+2], acc[i][j+3]);
        }
    }
}

// -------- per-node attention logits, layer 1: thread per (node, head) --------
__global__ void alpha1_k(const float* __restrict__ as1, const float* __restrict__ ad1) {
    int t = blockIdx.x * blockDim.x + threadIdx.x;
    if (t >= N_NODES * 8) return;
    const int n = t >> 3, h = t & 7;
    const float4* hp = (const float4*)g_h1 + n * 32 + h * 4;
    const float4* ap = (const float4*)as1 + h * 4;
    const float4* dp = (const float4*)ad1 + h * 4;
    float s = 0.f, d = 0.f;
#pragma unroll
    for (int i = 0; i < 4; i++) {
        float4 hv = hp[i], av = ap[i], dv = dp[i];
        s += hv.x * av.x + hv.y * av.y + hv.z * av.z + hv.w * av.w;
        d += hv.x * dv.x + hv.y * dv.y + hv.z * dv.z + hv.w * dv.w;
    }
    g_nas1[t] = s;
    g_nad1[t] = d;
}

// -------- layer-1 aggregate: warp per node, CSR gather, in-register softmax ---
__global__ void agg1_k() {
    const int warp = (blockIdx.x * blockDim.x + threadIdx.x) >> 5;
    const int lane = threadIdx.x & 31;
    if (warp >= N_NODES) return;
    const int n = warp;
    const int rs = g_rowptr[n], re = g_rowptr[n + 1];
    const float nadh = (lane < 8) ? g_nad1[n * 8 + lane] : 0.f;
    float den = 0.f;
    float4 acc = make_float4(0.f, 0.f, 0.f, 0.f);
    const int hsel = lane >> 2;   // source lane holding this float4's head ev
    for (int j = rs; j < re; j++) {
        const int src = g_esrc[j];
        float ev = 0.f;
        if (lane < 8) {
            float v = g_nas1[src * 8 + lane] + nadh;
            v = v > 0.f ? v : 0.2f * v;
            ev = expf(v);
            den += ev;
        }
        const float a = __shfl_sync(0xFFFFFFFFu, ev, hsel);
        float4 hv = ((const float4*)g_h1)[src * 32 + lane];
        acc.x += hv.x * a; acc.y += hv.y * a;
        acc.z += hv.z * a; acc.w += hv.w * a;
    }
    const float dh = __shfl_sync(0xFFFFFFFFu, den, hsel);
    const float inv = 1.f / (dh + 1e-16f);
    acc.x *= inv; acc.y *= inv; acc.z *= inv; acc.w *= inv;
    ((float4*)g_agg1)[n * 32 + lane] = acc;
}

// -------- per-node attention logits, layer 2: thread per node --------
__global__ void alpha2_k(const float* __restrict__ as2, const float* __restrict__ ad2) {
    int n = blockIdx.x * blockDim.x + threadIdx.x;
    if (n >= N_NODES) return;
    const float4* hp = (const float4*)g_h2 + n * 16;
    const float4* ap = (const float4*)as2;
    const float4* dp = (const float4*)ad2;
    float s = 0.f, d = 0.f;
#pragma unroll
    for (int i = 0; i < 16; i++) {
        float4 hv = hp[i], av = ap[i], dv = dp[i];
        s += hv.x * av.x + hv.y * av.y + hv.z * av.z + hv.w * av.w;
        d += hv.x * dv.x + hv.y * dv.y + hv.z * dv.z + hv.w * dv.w;
    }
    g_nas2[n] = s;
    g_nad2[n] = d;
}

// -------- layer-2 aggregate + bias + log_softmax: warp per node (2 edges/iter)
__global__ void agg2_k(float* __restrict__ out, const float* __restrict__ b2) {
    const int warp = (blockIdx.x * blockDim.x + threadIdx.x) >> 5;
    const int lane = threadIdx.x & 31;
    if (warp >= N_NODES) return;
    const int n = warp;
    const int rs = g_rowptr[n], re = g_rowptr[n + 1];
    const int grp = lane >> 4, ql = lane & 15;
    const float nad = g_nad2[n];
    float den = 0.f;
    float4 acc = make_float4(0.f, 0.f, 0.f, 0.f);
    for (int j = rs + grp; j < re; j += 2) {
        const int src = g_esrc[j];
        float v = g_nas2[src] + nad;
        v = v > 0.f ? v : 0.2f * v;
        const float ev = expf(v);
        den += ev;
        float4 hv = ((const float4*)g_h2)[src * 16 + ql];
        acc.x += hv.x * ev; acc.y += hv.y * ev;
        acc.z += hv.z * ev; acc.w += hv.w * ev;
    }
    // combine the two edge groups; duplicate totals to both halves
    acc.x += __shfl_xor_sync(0xFFFFFFFFu, acc.x, 16);
    acc.y += __shfl_xor_sync(0xFFFFFFFFu, acc.y, 16);
    acc.z += __shfl_xor_sync(0xFFFFFFFFu, acc.z, 16);
    acc.w += __shfl_xor_sync(0xFFFFFFFFu, acc.w, 16);
    den   += __shfl_xor_sync(0xFFFFFFFFu, den,   16);
    const float inv = 1.f / (den + 1e-16f);
    const float4 bb = ((const float4*)b2)[ql];
    float4 v4;
    v4.x = acc.x * inv + bb.x;
    v4.y = acc.y * inv + bb.y;
    v4.z = acc.z * inv + bb.z;
    v4.w = acc.w * inv + bb.w;
    // log_softmax across the 64 row values (both halves hold identical copies)
    float mx = fmaxf(fmaxf(v4.x, v4.y), fmaxf(v4.z, v4.w));
#pragma unroll
    for (int o = 1; o < 16; o <<= 1)
        mx = fmaxf(mx, __shfl_xor_sync(0xFFFFFFFFu, mx, o));
    float s = expf(v4.x - mx) + expf(v4.y - mx) + expf(v4.z - mx) + expf(v4.w - mx);
#pragma unroll
    for (int o = 1; o < 16; o <<= 1)
        s += __shfl_xor_sync(0xFFFFFFFFu, s, o);
    const float lse = logf(s) + mx;
    if (grp == 0) {
        v4.x -= lse; v4.y -= lse; v4.z -= lse; v4.w -= lse;
        ((float4*)out)[n * 16 + ql] = v4;
    }
}

extern "C" void kernel_launch(void* const* d_in, const int* in_sizes, int n_in,
                              void* d_out, int out_size) {
    const float* x   = (const float*)d_in[0];
    const void*  ei  = d_in[1];                 // int32 or int64, auto-detected
    const float* W1  = (const float*)d_in[2];
    const float* as1 = (const float*)d_in[3];
    const float* ad1 = (const float*)d_in[4];
    const float* b1  = (const float*)d_in[5];
    const float* W2  = (const float*)d_in[6];
    const float* as2 = (const float*)d_in[7];
    const float* ad2 = (const float*)d_in[8];
    const float* b2  = (const float*)d_in[9];
    float* out = (float*)d_out;

    void *p_h1, *p_agg1, *p_h2;
    cudaGetSymbolAddress(&p_h1,   g_h1);
    cudaGetSymbolAddress(&p_agg1, g_agg1);
    cudaGetSymbolAddress(&p_h2,   g_h2);

    const int gemm_blocks = (N_NODES + 127) / 128;   // 391
    const int warp_blocks = (N_NODES * 32 + 255) / 256;

    detect_k<<<1, 32>>>(ei);
    zerocnt_k<<<(N_NODES + 255) / 256, 256>>>();
    decode_hist_k<<<(ET + 255) / 256, 256>>>(ei);
    scan_k<<<1, 1024>>>();
    scatter_k<<<(ET + 255) / 256, 256>>>();
    gemm128<128, 8, false><<<gemm_blocks, 512>>>(x, W1, nullptr, (float*)p_h1);
    alpha1_k<<<(N_NODES * 8 + 255) / 256, 256>>>(as1, ad1);
    agg1_k<<<warp_blocks, 256>>>();
    gemm128<64, 4, true><<<gemm_blocks, 512>>>((const float*)p_agg1, W2, b1, (float*)p_h2);
    alpha2_k<<<(N_NODES + 255) / 256, 256>>>(as2, ad2);
    agg2_k<<<warp_blocks, 256>>>(out, b2);
}

// round 6
// speedup vs baseline: 1.3435x; 1.2977x over previous
#include <cuda_runtime.h>
#include <cuda_bf16.h>

// ---------------------------------------------------------------------------
// MultiGAT: 2-layer GAT on GB300, CSR gather-aggregate formulation (no float
// atomics). Softmax max-shift omitted (mathematically identical ratio).
// edge_index dtype (int32 vs int64) auto-detected on device.
// CSR rowptr built with a fully parallel 3-stage scan.
// ---------------------------------------------------------------------------

#define N_NODES 50000
#define NE      800000
#define ET      850000   // NE + N_NODES self loops
#define NBLK    ((N_NODES + 127) / 128)   // 391 scan blocks

// -------- scratch (device globals; allocation-free) --------
__device__ __align__(16) float g_h1  [N_NODES * 128];
__device__ __align__(16) float g_agg1[N_NODES * 128];
__device__ __align__(16) float g_h2  [N_NODES * 64];
__device__ float g_nas1[N_NODES * 8];
__device__ float g_nad1[N_NODES * 8];
__device__ float g_nas2[N_NODES];
__device__ float g_nad2[N_NODES];
__device__ int   g_src [ET];
__device__ int   g_dst [ET];
__device__ int   g_esrc[ET];            // CSR: src per slot, sorted by dst
__device__ int   g_rowptr[N_NODES + 1];
__device__ int   g_woff[N_NODES];
__device__ int   g_cnt [N_NODES];
__device__ int   g_bsum[NBLK];
__device__ int   g_boff[NBLK];
__device__ int   g_is64;

__device__ __forceinline__ float eluf(float v) {
    return v > 0.f ? v : expm1f(v);
}

// -------- dtype probe: int64 iff first 64 int64-reads are all valid indices --------
__global__ void detect_k(const void* __restrict__ ei) {
    if (threadIdx.x == 0 && blockIdx.x == 0) {
        const long long* p = (const long long*)ei;
        int ok = 1;
#pragma unroll 4
        for (int i = 0; i < 64; i++) {
            long long v = p[i];
            if (v < 0 || v >= N_NODES) ok = 0;
        }
        g_is64 = ok;
    }
}

__global__ void zerocnt_k() {
    int t = blockIdx.x * blockDim.x + threadIdx.x;
    if (t < N_NODES) g_cnt[t] = 0;
}

// -------- decode edge list (+ self loops) into int32 src/dst + dst histogram ---
__global__ void decode_hist_k(const void* __restrict__ ei) {
    int e = blockIdx.x * blockDim.x + threadIdx.x;
    if (e >= ET) return;
    int s, d;
    if (e < NE) {
        if (g_is64) {
            const long long* p = (const long long*)ei;
            s = (int)p[e];
            d = (int)p[NE + e];
        } else {
            const int* p = (const int*)ei;
            s = p[e];
            d = p[NE + e];
        }
    } else {
        s = d = e - NE;
    }
    g_src[e] = s;
    g_dst[e] = d;
    atomicAdd(&g_cnt[d], 1);
}

// -------- parallel scan stage 1: per-block sums of g_cnt --------
__global__ void partial_k() {
    __shared__ int wsum[4];
    const int t = threadIdx.x;                 // 128 threads
    const int i = blockIdx.x * 128 + t;
    int v = (i < N_NODES) ? g_cnt[i] : 0;
#pragma unroll
    for (int o = 16; o > 0; o >>= 1) v += __shfl_xor_sync(0xFFFFFFFFu, v, o);
    if ((t & 31) == 0) wsum[t >> 5] = v;
    __syncthreads();
    if (t == 0) g_bsum[blockIdx.x] = wsum[0] + wsum[1] + wsum[2] + wsum[3];
}

// -------- parallel scan stage 2: exclusive scan of NBLK block sums --------
__global__ void midscan_k() {
    __shared__ int wpre[16];
    const int t = threadIdx.x;                 // 512 threads
    const int lane = t & 31, w = t >> 5;
    int v = (t < NBLK) ? g_bsum[t] : 0;
    int inc = v;
#pragma unroll
    for (int o = 1; o < 32; o <<= 1) {
        int u = __shfl_up_sync(0xFFFFFFFFu, inc, o);
        if (lane >= o) inc += u;
    }
    if (lane == 31) wpre[w] = inc;
    __syncthreads();
    if (w == 0 && lane < 16) {
        int s = wpre[lane];
        int si = s;
#pragma unroll
        for (int o = 1; o < 16; o <<= 1) {
            int u = __shfl_up_sync(0xFFFFu, si, o);
            if (lane >= o) si += u;
        }
        wpre[lane] = si - s;   // exclusive warp offsets
    }
    __syncthreads();
    if (t < NBLK) g_boff[t] = inc - v + wpre[w];
    if (t == 0) g_rowptr[N_NODES] = ET;
}

// -------- parallel scan stage 3: in-block exclusive scan + base offset --------
__global__ void emit_k() {
    __shared__ int wpre[4];
    const int t = threadIdx.x;                 // 128 threads
    const int lane = t & 31, w = t >> 5;
    const int i = blockIdx.x * 128 + t;
    int v = (i < N_NODES) ? g_cnt[i] : 0;
    int inc = v;
#pragma unroll
    for (int o = 1; o < 32; o <<= 1) {
        int u = __shfl_up_sync(0xFFFFFFFFu, inc, o);
        if (lane >= o) inc += u;
    }
    if (lane == 31) wpre[w] = inc;
    __syncthreads();
    if (t == 0) {
        int run = 0;
#pragma unroll
        for (int k = 0; k < 4; k++) { int u = wpre[k]; wpre[k] = run; run += u; }
    }
    __syncthreads();
    if (i < N_NODES) {
        const int ex = inc - v + wpre[w] + g_boff[blockIdx.x];
        g_rowptr[i] = ex;
        g_woff[i]   = ex;
    }
}

// -------- scatter edges into CSR slots --------
__global__ void scatter_k() {
    int e = blockIdx.x * blockDim.x + threadIdx.x;
    if (e >= ET) return;
    int slot = atomicAdd(&g_woff[g_dst[e]], 1);
    g_esrc[slot] = g_src[e];
}

// -------- tiled SGEMM: C[M,BN] = A[M,128] @ B[128,BN], 512 thr, 4xTN tiles ----
template<int BN, int TN, bool FUSE>
__global__ __launch_bounds__(512)
void gemm128(const float* __restrict__ A, const float* __restrict__ B,
             const float* __restrict__ bias, float* __restrict__ C) {
    constexpr int BM = 128, BK = 16, K = 128;
    __shared__ float As[BK][BM + 4];
    __shared__ float Bs[BK][BN];
    const int tid = threadIdx.x;          // 512 threads
    const int tx = tid & 15;              // 16 col groups * TN = BN
    const int ty = tid >> 4;              // 32 row groups * 4 = 128
    const int rowBase = blockIdx.x * BM;

    float acc[4][TN];
#pragma unroll
    for (int i = 0; i < 4; i++)
#pragma unroll
        for (int j = 0; j < TN; j++) acc[i][j] = 0.f;

    for (int kt = 0; kt < K; kt += BK) {
        // A tile (transposed into smem): one float4 per thread
        {
            const int r  = tid >> 2;              // 0..127
            const int kg = (tid & 3) * 4;         // 0,4,8,12
            const int row = rowBase + r;
            float4 v = make_float4(0.f, 0.f, 0.f, 0.f);
            if (row < N_NODES)
                v = *(const float4*)&A[row * K + kt + kg];
            if (FUSE) {
                v.x = eluf(v.x + bias[kt + kg + 0]);
                v.y = eluf(v.y + bias[kt + kg + 1]);
                v.z = eluf(v.z + bias[kt + kg + 2]);
                v.w = eluf(v.w + bias[kt + kg + 3]);
            }
            As[kg + 0][r] = v.x;
            As[kg + 1][r] = v.y;
            As[kg + 2][r] = v.z;
            As[kg + 3][r] = v.w;
        }
        // B tile: 16 x BN contiguous
        {
            constexpr int TOT4 = BK * BN / 4;
            const float4* src4 = (const float4*)&B[kt * BN];
            float4* dst4 = (float4*)&Bs[0][0];
#pragma unroll
            for (int i = tid; i < TOT4; i += 512) dst4[i] = src4[i];
        }
        __syncthreads();
#pragma unroll
        for (int kk = 0; kk < BK; kk++) {
            float a[4], b[TN];
            float4 a0 = *(const float4*)&As[kk][ty * 4];
            a[0]=a0.x; a[1]=a0.y; a[2]=a0.z; a[3]=a0.w;
            float4 b0 = *(const float4*)&Bs[kk][tx * TN];
            b[0]=b0.x; b[1]=b0.y; b[2]=b0.z; b[3]=b0.w;
            if (TN == 8) {
                float4 b1 = *(const float4*)&Bs[kk][tx * TN + 4];
                b[4]=b1.x; b[5]=b1.y; b[6]=b1.z; b[7]=b1.w;
            }
#pragma unroll
            for (int i = 0; i < 4; i++)
#pragma unroll
                for (int j = 0; j < TN; j++) acc[i][j] += a[i] * b[j];
        }
        __syncthreads();
    }
#pragma unroll
    for (int i = 0; i < 4; i++) {
        const int row = rowBase + ty * 4 + i;
        if (row < N_NODES) {
#pragma unroll
            for (int j = 0; j < TN; j += 4)
                *(float4*)&C[row * BN + tx * TN + j] =
                    make_float4(acc[i][j], acc[i][j+1], acc[i][j+2], acc[i][j+3]);
        }
    }
}

// -------- per-node attention logits, layer 1: thread per (node, head) --------
__global__ void alpha1_k(const float* __restrict__ as1, const float* __restrict__ ad1) {
    int t = blockIdx.x * blockDim.x + threadIdx.x;
    if (t >= N_NODES * 8) return;
    const int n = t >> 3, h = t & 7;
    const float4* hp = (const float4*)g_h1 + n * 32 + h * 4;
    const float4* ap = (const float4*)as1 + h * 4;
    const float4* dp = (const float4*)ad1 + h * 4;
    float s = 0.f, d = 0.f;
#pragma unroll
    for (int i = 0; i < 4; i++) {
        float4 hv = hp[i], av = ap[i], dv = dp[i];
        s += hv.x * av.x + hv.y * av.y + hv.z * av.z + hv.w * av.w;
        d += hv.x * dv.x + hv.y * dv.y + hv.z * dv.z + hv.w * dv.w;
    }
    g_nas1[t] = s;
    g_nad1[t] = d;
}

// -------- layer-1 aggregate: warp per node, CSR gather, in-register softmax ---
__global__ void agg1_k() {
    const int warp = (blockIdx.x * blockDim.x + threadIdx.x) >> 5;
    const int lane = threadIdx.x & 31;
    if (warp >= N_NODES) return;
    const int n = warp;
    const int rs = g_rowptr[n], re = g_rowptr[n + 1];
    const float nadh = (lane < 8) ? g_nad1[n * 8 + lane] : 0.f;
    float den = 0.f;
    float4 acc = make_float4(0.f, 0.f, 0.f, 0.f);
    const int hsel = lane >> 2;   // source lane holding this float4's head ev
    for (int j = rs; j < re; j++) {
        const int src = g_esrc[j];
        float ev = 0.f;
        if (lane < 8) {
            float v = g_nas1[src * 8 + lane] + nadh;
            v = v > 0.f ? v : 0.2f * v;
            ev = expf(v);
            den += ev;
        }
        const float a = __shfl_sync(0xFFFFFFFFu, ev, hsel);
        float4 hv = ((const float4*)g_h1)[src * 32 + lane];
        acc.x += hv.x * a; acc.y += hv.y * a;
        acc.z += hv.z * a; acc.w += hv.w * a;
    }
    const float dh = __shfl_sync(0xFFFFFFFFu, den, hsel);
    const float inv = 1.f / (dh + 1e-16f);
    acc.x *= inv; acc.y *= inv; acc.z *= inv; acc.w *= inv;
    ((float4*)g_agg1)[n * 32 + lane] = acc;
}

// -------- per-node attention logits, layer 2: thread per node --------
__global__ void alpha2_k(const float* __restrict__ as2, const float* __restrict__ ad2) {
    int n = blockIdx.x * blockDim.x + threadIdx.x;
    if (n >= N_NODES) return;
    const float4* hp = (const float4*)g_h2 + n * 16;
    const float4* ap = (const float4*)as2;
    const float4* dp = (const float4*)ad2;
    float s = 0.f, d = 0.f;
#pragma unroll
    for (int i = 0; i < 16; i++) {
        float4 hv = hp[i], av = ap[i], dv = dp[i];
        s += hv.x * av.x + hv.y * av.y + hv.z * av.z + hv.w * av.w;
        d += hv.x * dv.x + hv.y * dv.y + hv.z * dv.z + hv.w * dv.w;
    }
    g_nas2[n] = s;
    g_nad2[n] = d;
}

// -------- layer-2 aggregate + bias + log_softmax: warp per node (2 edges/iter)
__global__ void agg2_k(float* __restrict__ out, const float* __restrict__ b2) {
    const int warp = (blockIdx.x * blockDim.x + threadIdx.x) >> 5;
    const int lane = threadIdx.x & 31;
    if (warp >= N_NODES) return;
    const int n = warp;
    const int rs = g_rowptr[n], re = g_rowptr[n + 1];
    const int grp = lane >> 4, ql = lane & 15;
    const float nad = g_nad2[n];
    float den = 0.f;
    float4 acc = make_float4(0.f, 0.f, 0.f, 0.f);
    for (int j = rs + grp; j < re; j += 2) {
        const int src = g_esrc[j];
        float v = g_nas2[src] + nad;
        v = v > 0.f ? v : 0.2f * v;
        const float ev = expf(v);
        den += ev;
        float4 hv = ((const float4*)g_h2)[src * 16 + ql];
        acc.x += hv.x * ev; acc.y += hv.y * ev;
        acc.z += hv.z * ev; acc.w += hv.w * ev;
    }
    // combine the two edge groups; duplicate totals to both halves
    acc.x += __shfl_xor_sync(0xFFFFFFFFu, acc.x, 16);
    acc.y += __shfl_xor_sync(0xFFFFFFFFu, acc.y, 16);
    acc.z += __shfl_xor_sync(0xFFFFFFFFu, acc.z, 16);
    acc.w += __shfl_xor_sync(0xFFFFFFFFu, acc.w, 16);
    den   += __shfl_xor_sync(0xFFFFFFFFu, den,   16);
    const float inv = 1.f / (den + 1e-16f);
    const float4 bb = ((const float4*)b2)[ql];
    float4 v4;
    v4.x = acc.x * inv + bb.x;
    v4.y = acc.y * inv + bb.y;
    v4.z = acc.z * inv + bb.z;
    v4.w = acc.w * inv + bb.w;
    // log_softmax across the 64 row values (both halves hold identical copies)
    float mx = fmaxf(fmaxf(v4.x, v4.y), fmaxf(v4.z, v4.w));
#pragma unroll
    for (int o = 1; o < 16; o <<= 1)
        mx = fmaxf(mx, __shfl_xor_sync(0xFFFFFFFFu, mx, o));
    float s = expf(v4.x - mx) + expf(v4.y - mx) + expf(v4.z - mx) + expf(v4.w - mx);
#pragma unroll
    for (int o = 1; o < 16; o <<= 1)
        s += __shfl_xor_sync(0xFFFFFFFFu, s, o);
    const float lse = logf(s) + mx;
    if (grp == 0) {
        v4.x -= lse; v4.y -= lse; v4.z -= lse; v4.w -= lse;
        ((float4*)out)[n * 16 + ql] = v4;
    }
}

extern "C" void kernel_launch(void* const* d_in, const int* in_sizes, int n_in,
                              void* d_out, int out_size) {
    const float* x   = (const float*)d_in[0];
    const void*  ei  = d_in[1];                 // int32 or int64, auto-detected
    const float* W1  = (const float*)d_in[2];
    const float* as1 = (const float*)d_in[3];
    const float* ad1 = (const float*)d_in[4];
    const float* b1  = (const float*)d_in[5];
    const float* W2  = (const float*)d_in[6];
    const float* as2 = (const float*)d_in[7];
    const float* ad2 = (const float*)d_in[8];
    const float* b2  = (const float*)d_in[9];
    float* out = (float*)d_out;

    void *p_h1, *p_agg1, *p_h2;
    cudaGetSymbolAddress(&p_h1,   g_h1);
    cudaGetSymbolAddress(&p_agg1, g_agg1);
    cudaGetSymbolAddress(&p_h2,   g_h2);

    const int gemm_blocks = (N_NODES + 127) / 128;   // 391
    const int warp_blocks = (N_NODES * 32 + 255) / 256;

    detect_k<<<1, 32>>>(ei);
    zerocnt_k<<<(N_NODES + 255) / 256, 256>>>();
    decode_hist_k<<<(ET + 255) / 256, 256>>>(ei);
    partial_k<<<NBLK, 128>>>();
    midscan_k<<<1, 512>>>();
    emit_k<<<NBLK, 128>>>();
    scatter_k<<<(ET + 255) / 256, 256>>>();
    gemm128<128, 8, false><<<gemm_blocks, 512>>>(x, W1, nullptr, (float*)p_h1);
    alpha1_k<<<(N_NODES * 8 + 255) / 256, 256>>>(as1, ad1);
    agg1_k<<<warp_blocks, 256>>>();
    gemm128<64, 4, true><<<gemm_blocks, 512>>>((const float*)p_agg1, W2, b1, (float*)p_h2);
    alpha2_k<<<(N_NODES + 255) / 256, 256>>>(as2, ad2);
    agg2_k<<<warp_blocks, 256>>>(out, b2);
}

// round 8
// speedup vs baseline: 1.4490x; 1.0786x over previous
#include <cuda_runtime.h>
#include <cuda_bf16.h>

// ---------------------------------------------------------------------------
// MultiGAT: 2-layer GAT on GB300, CSR gather-aggregate formulation.
// - No float atomics (per-dst CSR walk, in-register softmax; max-shift omitted:
//   mathematically identical ratio, values bounded).
// - edge_index dtype (int32 vs int64) auto-detected on device.
// - CSR build overlapped with GEMM1/alpha1 via fat kernels.
// - Aggregates process 4 edges/iteration for MLP on the L2 gather path.
// - All __shfl_sync calls execute warp-uniformly (R6 crash: divergent shfl).
// ---------------------------------------------------------------------------

#define N_NODES 50000
#define NE      800000
#define ET      850000                    // NE + N_NODES self loops
#define GEMM_BLOCKS ((N_NODES + 127) / 128)     // 391
#define SBLK        ((N_NODES + 511) / 512)     // 98 scan blocks (512 thr)
#define DEC_BLOCKS  160                          // hist blocks appended to GEMM1
#define ALPHA1_BLOCKS ((N_NODES * 8 + 511) / 512)  // 782

// -------- scratch (device globals; allocation-free) --------
__device__ __align__(16) float g_h1  [N_NODES * 128];
__device__ __align__(16) float g_agg1[N_NODES * 128];
__device__ __align__(16) float g_h2  [N_NODES * 64];
__device__ float g_nas1[N_NODES * 8];
__device__ float g_nad1[N_NODES * 8];
__device__ float g_nas2[N_NODES];
__device__ float g_nad2[N_NODES];
__device__ int   g_esrc[ET];            // CSR: src per slot, grouped by dst
__device__ int   g_rowptr[N_NODES + 1];
__device__ int   g_woff[N_NODES];
__device__ int   g_cnt [N_NODES];
__device__ int   g_bsum[SBLK];
__device__ int   g_boff[SBLK];
__device__ int   g_is64;

__device__ __forceinline__ float eluf(float v) {
    return v > 0.f ? v : expm1f(v);
}

// -------- decode helpers --------
__device__ __forceinline__ int edge_dst(const void* ei, int e, int is64) {
    if (e >= NE) return e - NE;
    return is64 ? (int)((const long long*)ei)[NE + e] : ((const int*)ei)[NE + e];
}
__device__ __forceinline__ int edge_src(const void* ei, int e, int is64) {
    if (e >= NE) return e - NE;
    return is64 ? (int)((const long long*)ei)[e] : ((const int*)ei)[e];
}

// -------- init: zero histogram + dtype probe --------
__global__ void init_k(const void* __restrict__ ei) {
    int t = blockIdx.x * blockDim.x + threadIdx.x;
    if (t < N_NODES) g_cnt[t] = 0;
    if (t == 0) {
        const long long* p = (const long long*)ei;
        int ok = 1;
#pragma unroll 4
        for (int i = 0; i < 64; i++) {
            long long v = p[i];
            if (v < 0 || v >= N_NODES) ok = 0;
        }
        g_is64 = ok;
    }
}

// -------- tiled SGEMM body: C[M,BN] = A[M,128] @ B[128,BN] --------
template<int BN, int TN, bool FUSE>
__device__ __forceinline__
void gemm_body(const float* __restrict__ A, const float* __restrict__ B,
               const float* __restrict__ bias, float* __restrict__ C, int bid) {
    constexpr int BM = 128, BK = 16, K = 128;
    __shared__ float As[BK][BM + 4];
    __shared__ float Bs[BK][BN];
    const int tid = threadIdx.x;          // 512 threads
    const int tx = tid & 15;              // 16 col groups * TN = BN
    const int ty = tid >> 4;              // 32 row groups * 4 = 128
    const int rowBase = bid * BM;

    float acc[4][TN];
#pragma unroll
    for (int i = 0; i < 4; i++)
#pragma unroll
        for (int j = 0; j < TN; j++) acc[i][j] = 0.f;

    for (int kt = 0; kt < K; kt += BK) {
        {
            const int r  = tid >> 2;              // 0..127
            const int kg = (tid & 3) * 4;         // 0,4,8,12
            const int row = rowBase + r;
            float4 v = make_float4(0.f, 0.f, 0.f, 0.f);
            if (row < N_NODES)
                v = *(const float4*)&A[row * K + kt + kg];
            if (FUSE) {
                v.x = eluf(v.x + bias[kt + kg + 0]);
                v.y = eluf(v.y + bias[kt + kg + 1]);
                v.z = eluf(v.z + bias[kt + kg + 2]);
                v.w = eluf(v.w + bias[kt + kg + 3]);
            }
            As[kg + 0][r] = v.x;
            As[kg + 1][r] = v.y;
            As[kg + 2][r] = v.z;
            As[kg + 3][r] = v.w;
        }
        {
            constexpr int TOT4 = BK * BN / 4;
            const float4* src4 = (const float4*)&B[kt * BN];
            float4* dst4 = (float4*)&Bs[0][0];
#pragma unroll
            for (int i = tid; i < TOT4; i += 512) dst4[i] = src4[i];
        }
        __syncthreads();
#pragma unroll
        for (int kk = 0; kk < BK; kk++) {
            float a[4], b[TN];
            float4 a0 = *(const float4*)&As[kk][ty * 4];
            a[0]=a0.x; a[1]=a0.y; a[2]=a0.z; a[3]=a0.w;
            float4 b0 = *(const float4*)&Bs[kk][tx * TN];
            b[0]=b0.x; b[1]=b0.y; b[2]=b0.z; b[3]=b0.w;
            if (TN == 8) {
                float4 b1 = *(const float4*)&Bs[kk][tx * TN + 4];
                b[4]=b1.x; b[5]=b1.y; b[6]=b1.z; b[7]=b1.w;
            }
#pragma unroll
            for (int i = 0; i < 4; i++)
#pragma unroll
                for (int j = 0; j < TN; j++) acc[i][j] += a[i] * b[j];
        }
        __syncthreads();
    }
#pragma unroll
    for (int i = 0; i < 4; i++) {
        const int row = rowBase + ty * 4 + i;
        if (row < N_NODES) {
#pragma unroll
            for (int j = 0; j < TN; j += 4)
                *(float4*)&C[row * BN + tx * TN + j] =
                    make_float4(acc[i][j], acc[i][j+1], acc[i][j+2], acc[i][j+3]);
        }
    }
}

// -------- fat kernel 1: GEMM1 blocks + dst-histogram blocks --------
__global__ __launch_bounds__(512)
void fat1_k(const float* __restrict__ x, const float* __restrict__ W1,
            const void* __restrict__ ei) {
    if (blockIdx.x < GEMM_BLOCKS) {
        gemm_body<128, 8, false>(x, W1, nullptr, g_h1, blockIdx.x);
    } else {
        const int is64 = g_is64;
        const int b = blockIdx.x - GEMM_BLOCKS;
        for (int e = b * 512 + threadIdx.x; e < ET; e += DEC_BLOCKS * 512)
            atomicAdd(&g_cnt[edge_dst(ei, e, is64)], 1);
    }
}

// -------- fat kernel 2: alpha1 blocks + scan-stage-1 blocks --------
__global__ __launch_bounds__(512)
void fat2_k(const float* __restrict__ as1, const float* __restrict__ ad1) {
    if (blockIdx.x < ALPHA1_BLOCKS) {
        int t = blockIdx.x * 512 + threadIdx.x;
        if (t >= N_NODES * 8) return;
        const int n = t >> 3, h = t & 7;
        const float4* hp = (const float4*)g_h1 + n * 32 + h * 4;
        const float4* ap = (const float4*)as1 + h * 4;
        const float4* dp = (const float4*)ad1 + h * 4;
        float s = 0.f, d = 0.f;
#pragma unroll
        for (int i = 0; i < 4; i++) {
            float4 hv = hp[i], av = ap[i], dv = dp[i];
            s += hv.x * av.x + hv.y * av.y + hv.z * av.z + hv.w * av.w;
            d += hv.x * dv.x + hv.y * dv.y + hv.z * dv.z + hv.w * dv.w;
        }
        g_nas1[t] = s;
        g_nad1[t] = d;
    } else {
        __shared__ int wsum[16];
        const int b = blockIdx.x - ALPHA1_BLOCKS;
        const int t = threadIdx.x, lane = t & 31, w = t >> 5;
        const int i = b * 512 + t;
        int v = (i < N_NODES) ? g_cnt[i] : 0;
#pragma unroll
        for (int o = 16; o > 0; o >>= 1) v += __shfl_xor_sync(0xFFFFFFFFu, v, o);
        if (lane == 0) wsum[w] = v;
        __syncthreads();
        if (t == 0) {
            int s = 0;
#pragma unroll
            for (int k = 0; k < 16; k++) s += wsum[k];
            g_bsum[b] = s;
        }
    }
}

// -------- scan stage 2: exclusive scan of SBLK block sums --------
__global__ void midscan_k() {
    __shared__ int wpre[16];
    const int t = threadIdx.x;                 // 512 threads
    const int lane = t & 31, w = t >> 5;
    int v = (t < SBLK) ? g_bsum[t] : 0;
    int inc = v;
#pragma unroll
    for (int o = 1; o < 32; o <<= 1) {
        int u = __shfl_up_sync(0xFFFFFFFFu, inc, o);
        if (lane >= o) inc += u;
    }
    if (lane == 31) wpre[w] = inc;
    __syncthreads();
    if (w == 0 && lane < 16) {
        int s = wpre[lane];
        int si = s;
#pragma unroll
        for (int o = 1; o < 16; o <<= 1) {
            int u = __shfl_up_sync(0xFFFFu, si, o);
            if (lane >= o) si += u;
        }
        wpre[lane] = si - s;   // exclusive warp offsets
    }
    __syncthreads();
    if (t < SBLK) g_boff[t] = inc - v + wpre[w];
    if (t == 0) g_rowptr[N_NODES] = ET;
}

// -------- scan stage 3: in-block exclusive scan + base offset --------
__global__ void emit_k() {
    __shared__ int wpre[16];
    const int t = threadIdx.x;                 // 512 threads
    const int lane = t & 31, w = t >> 5;
    const int i = blockIdx.x * 512 + t;
    int v = (i < N_NODES) ? g_cnt[i] : 0;
    int inc = v;
#pragma unroll
    for (int o = 1; o < 32; o <<= 1) {
        int u = __shfl_up_sync(0xFFFFFFFFu, inc, o);
        if (lane >= o) inc += u;
    }
    if (lane == 31) wpre[w] = inc;
    __syncthreads();
    if (t == 0) {
        int run = 0;
#pragma unroll
        for (int k = 0; k < 16; k++) { int u = wpre[k]; wpre[k] = run; run += u; }
    }
    __syncthreads();
    if (i < N_NODES) {
        const int ex = inc - v + wpre[w] + g_boff[blockIdx.x];
        g_rowptr[i] = ex;
        g_woff[i]   = ex;
    }
}

// -------- scatter edges into CSR slots (re-decode from edge_index) --------
__global__ void scatter_k(const void* __restrict__ ei) {
    int e = blockIdx.x * blockDim.x + threadIdx.x;
    if (e >= ET) return;
    const int is64 = g_is64;
    const int d = edge_dst(ei, e, is64);
    const int s = edge_src(ei, e, is64);
    int slot = atomicAdd(&g_woff[d], 1);
    g_esrc[slot] = s;
}

// -------- layer-1 aggregate: warp/node, 4 edges per iteration --------
// NOTE: the j+t<re guards are warp-uniform (j,t,re uniform per warp), so the
// shuffles inside them are warp-uniform too.
__global__ void agg1_k() {
    const int warp = (blockIdx.x * blockDim.x + threadIdx.x) >> 5;
    const int lane = threadIdx.x & 31;
    if (warp >= N_NODES) return;
    const int n = warp;
    const int rs = g_rowptr[n], re = g_rowptr[n + 1];
    const float nadh = g_nad1[n * 8 + (lane & 7)];
    const int hq = lane >> 2;          // head index of this lane's float4 (0..7)
    float den = 0.f;
    float4 acc = make_float4(0.f, 0.f, 0.f, 0.f);
    for (int j = rs; j < re; j += 4) {
        const int eidx = j + (lane >> 3);   // 8-lane group per edge
        int srcg = 0;
        float ev = 0.f;
        if (eidx < re) {
            srcg = g_esrc[eidx];
            float v = g_nas1[srcg * 8 + (lane & 7)] + nadh;
            v = v > 0.f ? v : 0.2f * v;
            ev = expf(v);
            den += ev;
        }
#pragma unroll
        for (int t = 0; t < 4; t++) {
            // warp-uniform guard -> shuffles execute warp-uniformly
            if (j + t < re) {
                const int   src = __shfl_sync(0xFFFFFFFFu, srcg, t * 8);
                const float a   = __shfl_sync(0xFFFFFFFFu, ev,   t * 8 + hq);
                float4 hv = ((const float4*)g_h1)[src * 32 + lane];
                acc.x += hv.x * a; acc.y += hv.y * a;
                acc.z += hv.z * a; acc.w += hv.w * a;
            }
        }
    }
    // per-head totals: lanes {h, h+8, h+16, h+24} hold partials for head h
    den += __shfl_xor_sync(0xFFFFFFFFu, den, 8);
    den += __shfl_xor_sync(0xFFFFFFFFu, den, 16);
    const float dh = __shfl_sync(0xFFFFFFFFu, den, hq);
    const float inv = 1.f / (dh + 1e-16f);
    acc.x *= inv; acc.y *= inv; acc.z *= inv; acc.w *= inv;
    ((float4*)g_agg1)[n * 32 + lane] = acc;
}

// -------- GEMM2: (ELU(agg1+b1)) @ W2 --------
__global__ __launch_bounds__(512)
void gemm2_k(const float* __restrict__ W2, const float* __restrict__ b1) {
    gemm_body<64, 4, true>(g_agg1, W2, b1, g_h2, blockIdx.x);
}

// -------- per-node attention logits, layer 2 --------
__global__ void alpha2_k(const float* __restrict__ as2, const float* __restrict__ ad2) {
    int n = blockIdx.x * blockDim.x + threadIdx.x;
    if (n >= N_NODES) return;
    const float4* hp = (const float4*)g_h2 + n * 16;
    const float4* ap = (const float4*)as2;
    const float4* dp = (const float4*)ad2;
    float s = 0.f, d = 0.f;
#pragma unroll
    for (int i = 0; i < 16; i++) {
        float4 hv = hp[i], av = ap[i], dv = dp[i];
        s += hv.x * av.x + hv.y * av.y + hv.z * av.z + hv.w * av.w;
        d += hv.x * dv.x + hv.y * dv.y + hv.z * dv.z + hv.w * dv.w;
    }
    g_nas2[n] = s;
    g_nad2[n] = d;
}

// -------- layer-2 aggregate + bias + log_softmax: warp/node, 4 edges/iter ----
// FIX vs R6: shuffles hoisted OUT of the lane-divergent guard (e0 depends on
// grp=lane>>4; divergent shfl_sync with full mask is UB -> garbage src ->
// illegal memory access). All lanes now execute every shuffle.
__global__ void agg2_k(float* __restrict__ out, const float* __restrict__ b2) {
    const int warp = (blockIdx.x * blockDim.x + threadIdx.x) >> 5;
    const int lane = threadIdx.x & 31;
    if (warp >= N_NODES) return;
    const int n = warp;
    const int rs = g_rowptr[n], re = g_rowptr[n + 1];
    const int grp = lane >> 4, ql = lane & 15;
    const float nad = g_nad2[n];
    float den = 0.f;
    float4 acc = make_float4(0.f, 0.f, 0.f, 0.f);
    for (int j = rs; j < re; j += 4) {
        const int idx = j + lane;
        int srcl = 0;
        float ev = 0.f;
        if (lane < 4 && idx < re) {
            srcl = g_esrc[idx];
            float v = g_nas2[srcl] + nad;
            v = v > 0.f ? v : 0.2f * v;
            ev = expf(v);
            den += ev;
        }
#pragma unroll
        for (int t = 0; t < 2; t++) {
            const int e0 = t * 2 + grp;     // group g handles edges j+g, j+2+g
            // shuffles unconditional (warp-uniform execution); guard only the use
            const int   src = __shfl_sync(0xFFFFFFFFu, srcl, e0);
            const float a   = __shfl_sync(0xFFFFFFFFu, ev,   e0);
            if (j + e0 < re) {
                float4 hv = ((const float4*)g_h2)[src * 16 + ql];
                acc.x += hv.x * a; acc.y += hv.y * a;
                acc.z += hv.z * a; acc.w += hv.w * a;
            }
        }
    }
    // den partials live in lanes 0..3
    den += __shfl_xor_sync(0xFFFFFFFFu, den, 1);
    den += __shfl_xor_sync(0xFFFFFFFFu, den, 2);
    den  = __shfl_sync(0xFFFFFFFFu, den, 0);
    // combine the two 16-lane groups' accumulators
    acc.x += __shfl_xor_sync(0xFFFFFFFFu, acc.x, 16);
    acc.y += __shfl_xor_sync(0xFFFFFFFFu, acc.y, 16);
    acc.z += __shfl_xor_sync(0xFFFFFFFFu, acc.z, 16);
    acc.w += __shfl_xor_sync(0xFFFFFFFFu, acc.w, 16);
    const float inv = 1.f / (den + 1e-16f);
    const float4 bb = ((const float4*)b2)[ql];
    float4 v4;
    v4.x = acc.x * inv + bb.x;
    v4.y = acc.y * inv + bb.y;
    v4.z = acc.z * inv + bb.z;
    v4.w = acc.w * inv + bb.w;
    // log_softmax across the 64 row values (both halves hold identical copies)
    float mx = fmaxf(fmaxf(v4.x, v4.y), fmaxf(v4.z, v4.w));
#pragma unroll
    for (int o = 1; o < 16; o <<= 1)
        mx = fmaxf(mx, __shfl_xor_sync(0xFFFFFFFFu, mx, o));
    float s = expf(v4.x - mx) + expf(v4.y - mx) + expf(v4.z - mx) + expf(v4.w - mx);
#pragma unroll
    for (int o = 1; o < 16; o <<= 1)
        s += __shfl_xor_sync(0xFFFFFFFFu, s, o);
    const float lse = logf(s) + mx;
    if (grp == 0) {
        v4.x -= lse; v4.y -= lse; v4.z -= lse; v4.w -= lse;
        ((float4*)out)[n * 16 + ql] = v4;
    }
}

extern "C" void kernel_launch(void* const* d_in, const int* in_sizes, int n_in,
                              void* d_out, int out_size) {
    const float* x   = (const float*)d_in[0];
    const void*  ei  = d_in[1];                 // int32 or int64, auto-detected
    const float* W1  = (const float*)d_in[2];
    const float* as1 = (const float*)d_in[3];
    const float* ad1 = (const float*)d_in[4];
    const float* b1  = (const float*)d_in[5];
    const float* W2  = (const float*)d_in[6];
    const float* as2 = (const float*)d_in[7];
    const float* ad2 = (const float*)d_in[8];
    const float* b2  = (const float*)d_in[9];
    float* out = (float*)d_out;

    const int warp_blocks = (N_NODES * 32 + 255) / 256;   // 6250

    init_k<<<SBLK, 512>>>(ei);
    fat1_k<<<GEMM_BLOCKS + DEC_BLOCKS, 512>>>(x, W1, ei);        // GEMM1 ∥ hist
    fat2_k<<<ALPHA1_BLOCKS + SBLK, 512>>>(as1, ad1);             // alpha1 ∥ scan-1
    midscan_k<<<1, 512>>>();
    emit_k<<<SBLK, 512>>>();
    scatter_k<<<(ET + 511) / 512, 512>>>(ei);
    agg1_k<<<warp_blocks, 256>>>();
    gemm2_k<<<GEMM_BLOCKS, 512>>>(W2, b1);
    alpha2_k<<<SBLK, 512>>>(as2, ad2);
    agg2_k<<<warp_blocks, 256>>>(out, b2);
}

// round 9
// speedup vs baseline: 1.6643x; 1.1486x over previous
#include <cuda_runtime.h>
#include <cuda_fp16.h>

// ---------------------------------------------------------------------------
// MultiGAT: 2-layer GAT on GB300, CSR gather-aggregate formulation.
// - Features h1/h2 stored fp16 (halves gather traffic); fp32 accumulation.
// - No float atomics (per-dst CSR walk, in-register softmax; max-shift omitted:
//   mathematically identical ratio, values bounded).
// - edge_index dtype (int32 vs int64) auto-detected on device.
// - CSR build overlapped with GEMM1/alpha1 via fat kernels.
// - All __shfl_sync calls execute warp-uniformly.
// ---------------------------------------------------------------------------

#define N_NODES 50000
#define NE      800000
#define ET      850000                    // NE + N_NODES self loops
#define GEMM_BLOCKS ((N_NODES + 127) / 128)     // 391
#define SBLK        ((N_NODES + 511) / 512)     // 98 scan blocks (512 thr)
#define DEC_BLOCKS  160                          // hist blocks appended to GEMM1
#define ALPHA1_BLOCKS ((N_NODES * 8 + 511) / 512)  // 782

// -------- scratch (device globals; allocation-free) --------
__device__ __align__(16) __half g_h1h [N_NODES * 128];
__device__ __align__(16) float  g_agg1[N_NODES * 128];
__device__ __align__(16) __half g_h2h [N_NODES * 64];
__device__ float g_nas1[N_NODES * 8];
__device__ float g_nad1[N_NODES * 8];
__device__ float g_nas2[N_NODES];
__device__ float g_nad2[N_NODES];
__device__ int   g_esrc[ET];            // CSR: src per slot, grouped by dst
__device__ int   g_rowptr[N_NODES + 1];
__device__ int   g_woff[N_NODES];
__device__ int   g_cnt [N_NODES];
__device__ int   g_bsum[SBLK];
__device__ int   g_boff[SBLK];
__device__ int   g_is64;

__device__ __forceinline__ float eluf(float v) {
    return v > 0.f ? v : expm1f(v);
}

// -------- decode helpers --------
__device__ __forceinline__ int edge_dst(const void* ei, int e, int is64) {
    if (e >= NE) return e - NE;
    return is64 ? (int)((const long long*)ei)[NE + e] : ((const int*)ei)[NE + e];
}
__device__ __forceinline__ int edge_src(const void* ei, int e, int is64) {
    if (e >= NE) return e - NE;
    return is64 ? (int)((const long long*)ei)[e] : ((const int*)ei)[e];
}

// -------- init: zero histogram + dtype probe --------
__global__ void init_k(const void* __restrict__ ei) {
    int t = blockIdx.x * blockDim.x + threadIdx.x;
    if (t < N_NODES) g_cnt[t] = 0;
    if (t == 0) {
        const long long* p = (const long long*)ei;
        int ok = 1;
#pragma unroll 4
        for (int i = 0; i < 64; i++) {
            long long v = p[i];
            if (v < 0 || v >= N_NODES) ok = 0;
        }
        g_is64 = ok;
    }
}

// -------- tiled SGEMM body: C[M,BN] = A[M,128] @ B[128,BN], fp16 output -----
template<int BN, int TN, bool FUSE>
__device__ __forceinline__
void gemm_body(const float* __restrict__ A, const float* __restrict__ B,
               const float* __restrict__ bias, __half* __restrict__ C, int bid) {
    constexpr int BM = 128, BK = 16, K = 128;
    __shared__ float As[BK][BM + 4];
    __shared__ float Bs[BK][BN];
    const int tid = threadIdx.x;          // 512 threads
    const int tx = tid & 15;              // 16 col groups * TN = BN
    const int ty = tid >> 4;              // 32 row groups * 4 = 128
    const int rowBase = bid * BM;

    float acc[4][TN];
#pragma unroll
    for (int i = 0; i < 4; i++)
#pragma unroll
        for (int j = 0; j < TN; j++) acc[i][j] = 0.f;

    for (int kt = 0; kt < K; kt += BK) {
        {
            const int r  = tid >> 2;              // 0..127
            const int kg = (tid & 3) * 4;         // 0,4,8,12
            const int row = rowBase + r;
            float4 v = make_float4(0.f, 0.f, 0.f, 0.f);
            if (row < N_NODES)
                v = *(const float4*)&A[row * K + kt + kg];
            if (FUSE) {
                v.x = eluf(v.x + bias[kt + kg + 0]);
                v.y = eluf(v.y + bias[kt + kg + 1]);
                v.z = eluf(v.z + bias[kt + kg + 2]);
                v.w = eluf(v.w + bias[kt + kg + 3]);
            }
            As[kg + 0][r] = v.x;
            As[kg + 1][r] = v.y;
            As[kg + 2][r] = v.z;
            As[kg + 3][r] = v.w;
        }
        {
            constexpr int TOT4 = BK * BN / 4;
            const float4* src4 = (const float4*)&B[kt * BN];
            float4* dst4 = (float4*)&Bs[0][0];
#pragma unroll
            for (int i = tid; i < TOT4; i += 512) dst4[i] = src4[i];
        }
        __syncthreads();
#pragma unroll
        for (int kk = 0; kk < BK; kk++) {
            float a[4], b[TN];
            float4 a0 = *(const float4*)&As[kk][ty * 4];
            a[0]=a0.x; a[1]=a0.y; a[2]=a0.z; a[3]=a0.w;
            float4 b0 = *(const float4*)&Bs[kk][tx * TN];
            b[0]=b0.x; b[1]=b0.y; b[2]=b0.z; b[3]=b0.w;
            if (TN == 8) {
                float4 b1 = *(const float4*)&Bs[kk][tx * TN + 4];
                b[4]=b1.x; b[5]=b1.y; b[6]=b1.z; b[7]=b1.w;
            }
#pragma unroll
            for (int i = 0; i < 4; i++)
#pragma unroll
                for (int j = 0; j < TN; j++) acc[i][j] += a[i] * b[j];
        }
        __syncthreads();
    }
#pragma unroll
    for (int i = 0; i < 4; i++) {
        const int row = rowBase + ty * 4 + i;
        if (row < N_NODES) {
            if (TN == 8) {
                __half2 h[4];
#pragma unroll
                for (int j = 0; j < 4; j++)
                    h[j] = __floats2half2_rn(acc[i][2*j], acc[i][2*j+1]);
                ((uint4*)C)[row * (BN / 8) + tx] = *(uint4*)h;
            } else {
                __half2 h[2];
                h[0] = __floats2half2_rn(acc[i][0], acc[i][1]);
                h[1] = __floats2half2_rn(acc[i][2], acc[i][3]);
                ((uint2*)C)[row * (BN / 4) + tx] = *(uint2*)h;
            }
        }
    }
}

// -------- fat kernel 1: GEMM1 blocks + dst-histogram blocks --------
__global__ __launch_bounds__(512)
void fat1_k(const float* __restrict__ x, const float* __restrict__ W1,
            const void* __restrict__ ei) {
    if (blockIdx.x < GEMM_BLOCKS) {
        gemm_body<128, 8, false>(x, W1, nullptr, g_h1h, blockIdx.x);
    } else {
        const int is64 = g_is64;
        const int b = blockIdx.x - GEMM_BLOCKS;
        for (int e = b * 512 + threadIdx.x; e < ET; e += DEC_BLOCKS * 512)
            atomicAdd(&g_cnt[edge_dst(ei, e, is64)], 1);
    }
}

// -------- fat kernel 2: alpha1 blocks + scan-stage-1 blocks --------
__global__ __launch_bounds__(512)
void fat2_k(const float* __restrict__ as1, const float* __restrict__ ad1) {
    if (blockIdx.x < ALPHA1_BLOCKS) {
        int t = blockIdx.x * 512 + threadIdx.x;
        if (t >= N_NODES * 8) return;
        const int n = t >> 3, h = t & 7;
        // 16 halves = 2 uint4 loads
        const uint4* hp = (const uint4*)(g_h1h + n * 128 + h * 16);
        const float4* ap = (const float4*)as1 + h * 4;
        const float4* dp = (const float4*)ad1 + h * 4;
        float s = 0.f, d = 0.f;
#pragma unroll
        for (int u = 0; u < 2; u++) {
            uint4 raw = hp[u];
            const __half2* h2p = (const __half2*)&raw;
#pragma unroll
            for (int i = 0; i < 2; i++) {
                float2 f0 = __half22float2(h2p[2*i]);
                float2 f1 = __half22float2(h2p[2*i+1]);
                float4 av = ap[u*2+i], dv = dp[u*2+i];
                s += f0.x*av.x + f0.y*av.y + f1.x*av.z + f1.y*av.w;
                d += f0.x*dv.x + f0.y*dv.y + f1.x*dv.z + f1.y*dv.w;
            }
        }
        g_nas1[t] = s;
        g_nad1[t] = d;
    } else {
        __shared__ int wsum[16];
        const int b = blockIdx.x - ALPHA1_BLOCKS;
        const int t = threadIdx.x, lane = t & 31, w = t >> 5;
        const int i = b * 512 + t;
        int v = (i < N_NODES) ? g_cnt[i] : 0;
#pragma unroll
        for (int o = 16; o > 0; o >>= 1) v += __shfl_xor_sync(0xFFFFFFFFu, v, o);
        if (lane == 0) wsum[w] = v;
        __syncthreads();
        if (t == 0) {
            int s = 0;
#pragma unroll
            for (int k = 0; k < 16; k++) s += wsum[k];
            g_bsum[b] = s;
        }
    }
}

// -------- scan stage 2: exclusive scan of SBLK block sums --------
__global__ void midscan_k() {
    __shared__ int wpre[16];
    const int t = threadIdx.x;                 // 512 threads
    const int lane = t & 31, w = t >> 5;
    int v = (t < SBLK) ? g_bsum[t] : 0;
    int inc = v;
#pragma unroll
    for (int o = 1; o < 32; o <<= 1) {
        int u = __shfl_up_sync(0xFFFFFFFFu, inc, o);
        if (lane >= o) inc += u;
    }
    if (lane == 31) wpre[w] = inc;
    __syncthreads();
    if (w == 0 && lane < 16) {
        int s = wpre[lane];
        int si = s;
#pragma unroll
        for (int o = 1; o < 16; o <<= 1) {
            int u = __shfl_up_sync(0xFFFFu, si, o);
            if (lane >= o) si += u;
        }
        wpre[lane] = si - s;   // exclusive warp offsets
    }
    __syncthreads();
    if (t < SBLK) g_boff[t] = inc - v + wpre[w];
    if (t == 0) g_rowptr[N_NODES] = ET;
}

// -------- scan stage 3: in-block exclusive scan + base offset --------
__global__ void emit_k() {
    __shared__ int wpre[16];
    const int t = threadIdx.x;                 // 512 threads
    const int lane = t & 31, w = t >> 5;
    const int i = blockIdx.x * 512 + t;
    int v = (i < N_NODES) ? g_cnt[i] : 0;
    int inc = v;
#pragma unroll
    for (int o = 1; o < 32; o <<= 1) {
        int u = __shfl_up_sync(0xFFFFFFFFu, inc, o);
        if (lane >= o) inc += u;
    }
    if (lane == 31) wpre[w] = inc;
    __syncthreads();
    if (t == 0) {
        int run = 0;
#pragma unroll
        for (int k = 0; k < 16; k++) { int u = wpre[k]; wpre[k] = run; run += u; }
    }
    __syncthreads();
    if (i < N_NODES) {
        const int ex = inc - v + wpre[w] + g_boff[blockIdx.x];
        g_rowptr[i] = ex;
        g_woff[i]   = ex;
    }
}

// -------- scatter edges into CSR slots (re-decode from edge_index) --------
__global__ void scatter_k(const void* __restrict__ ei) {
    int e = blockIdx.x * blockDim.x + threadIdx.x;
    if (e >= ET) return;
    const int is64 = g_is64;
    const int d = edge_dst(ei, e, is64);
    const int s = edge_src(ei, e, is64);
    int slot = atomicAdd(&g_woff[d], 1);
    g_esrc[slot] = s;
}

// -------- layer-1 aggregate: warp/node, fp16 gather, 4 edges/iter --------
// Row = 128 halves = 16 lanes x uint4; half-warp gathers one edge.
__global__ void agg1_k() {
    const int warp = (blockIdx.x * blockDim.x + threadIdx.x) >> 5;
    const int lane = threadIdx.x & 31;
    if (warp >= N_NODES) return;
    const int n = warp;
    const int rs = g_rowptr[n], re = g_rowptr[n + 1];
    const int ql  = lane & 15;         // channel group: owns channels ql*8..ql*8+7
    const int grp = lane >> 4;         // half-warp id (edge selector)
    const int hq  = ql >> 1;           // head of this lane's channels
    const float nadh = g_nad1[n * 8 + (lane & 7)];
    float den = 0.f;
    float accv[8];
#pragma unroll
    for (int k = 0; k < 8; k++) accv[k] = 0.f;

    for (int j = rs; j < re; j += 4) {
        const int eidx = j + (lane >> 3);   // lanes 8e..8e+7 handle edge j+e
        int srcg = 0;
        float ev = 0.f;
        if (eidx < re) {
            srcg = g_esrc[eidx];
            float v = g_nas1[srcg * 8 + (lane & 7)] + nadh;
            v = v > 0.f ? v : 0.2f * v;
            ev = __expf(v);
            den += ev;
        }
#pragma unroll
        for (int t = 0; t < 2; t++) {
            const int e0 = t * 2 + grp;     // this half-warp's edge this step
            // shuffles unconditional (warp-uniform execution)
            const int   src = __shfl_sync(0xFFFFFFFFu, srcg, e0 * 8);
            const float a   = __shfl_sync(0xFFFFFFFFu, ev,   e0 * 8 + hq);
            if (j + e0 < re) {
                uint4 raw = ((const uint4*)g_h1h)[src * 16 + ql];
                const __half2* h2p = (const __half2*)&raw;
#pragma unroll
                for (int k = 0; k < 4; k++) {
                    float2 f = __half22float2(h2p[k]);
                    accv[2*k]   += f.x * a;
                    accv[2*k+1] += f.y * a;
                }
            }
        }
    }
    // combine the two half-warps' accumulators
#pragma unroll
    for (int k = 0; k < 8; k++)
        accv[k] += __shfl_xor_sync(0xFFFFFFFFu, accv[k], 16);
    // per-head denom: partials for head h live in lanes {h, h+8, h+16, h+24}
    den += __shfl_xor_sync(0xFFFFFFFFu, den, 8);
    den += __shfl_xor_sync(0xFFFFFFFFu, den, 16);
    const float dh = __shfl_sync(0xFFFFFFFFu, den, hq);
    const float inv = 1.f / (dh + 1e-16f);
    if (grp == 0) {
        float4 o0 = make_float4(accv[0]*inv, accv[1]*inv, accv[2]*inv, accv[3]*inv);
        float4 o1 = make_float4(accv[4]*inv, accv[5]*inv, accv[6]*inv, accv[7]*inv);
        ((float4*)g_agg1)[n * 32 + ql * 2]     = o0;
        ((float4*)g_agg1)[n * 32 + ql * 2 + 1] = o1;
    }
}

// -------- GEMM2: (ELU(agg1+b1)) @ W2 -> fp16 h2 --------
__global__ __launch_bounds__(512)
void gemm2_k(const float* __restrict__ W2, const float* __restrict__ b1) {
    gemm_body<64, 4, true>(g_agg1, W2, b1, g_h2h, blockIdx.x);
}

// -------- per-node attention logits, layer 2 (fp16 features) --------
__global__ void alpha2_k(const float* __restrict__ as2, const float* __restrict__ ad2) {
    int n = blockIdx.x * blockDim.x + threadIdx.x;
    if (n >= N_NODES) return;
    const uint4* hp = (const uint4*)(g_h2h + n * 64);   // 64 halves = 8 uint4
    const float4* ap = (const float4*)as2;
    const float4* dp = (const float4*)ad2;
    float s = 0.f, d = 0.f;
#pragma unroll
    for (int u = 0; u < 8; u++) {
        uint4 raw = hp[u];
        const __half2* h2p = (const __half2*)&raw;
#pragma unroll
        for (int i = 0; i < 2; i++) {
            float2 f0 = __half22float2(h2p[2*i]);
            float2 f1 = __half22float2(h2p[2*i+1]);
            float4 av = ap[u*2+i], dv = dp[u*2+i];
            s += f0.x*av.x + f0.y*av.y + f1.x*av.z + f1.y*av.w;
            d += f0.x*dv.x + f0.y*dv.y + f1.x*dv.z + f1.y*dv.w;
        }
    }
    g_nas2[n] = s;
    g_nad2[n] = d;
}

// -------- layer-2 aggregate + bias + log_softmax: warp/node, 4 edges/iter ----
// Row = 64 halves = 8 lanes x uint4; quarter-warp gathers one edge.
__global__ void agg2_k(float* __restrict__ out, const float* __restrict__ b2) {
    const int warp = (blockIdx.x * blockDim.x + threadIdx.x) >> 5;
    const int lane = threadIdx.x & 31;
    if (warp >= N_NODES) return;
    const int n = warp;
    const int rs = g_rowptr[n], re = g_rowptr[n + 1];
    const int ql  = lane & 7;          // channel group: owns channels ql*8..ql*8+7
    const int grp = lane >> 3;         // quarter-warp id (edge selector, 0..3)
    const float nad = g_nad2[n];
    float den = 0.f;
    float accv[8];
#pragma unroll
    for (int k = 0; k < 8; k++) accv[k] = 0.f;

    for (int j = rs; j < re; j += 4) {
        const int idx = j + lane;
        int srcl = 0;
        float ev = 0.f;
        if (lane < 4 && idx < re) {
            srcl = g_esrc[idx];
            float v = g_nas2[srcl] + nad;
            v = v > 0.f ? v : 0.2f * v;
            ev = __expf(v);
            den += ev;
        }
        // each quarter-warp handles edge j+grp; shuffles unconditional
        const int   src = __shfl_sync(0xFFFFFFFFu, srcl, grp);
        const float a   = __shfl_sync(0xFFFFFFFFu, ev,   grp);
        if (j + grp < re) {
            uint4 raw = ((const uint4*)g_h2h)[src * 8 + ql];
            const __half2* h2p = (const __half2*)&raw;
#pragma unroll
            for (int k = 0; k < 4; k++) {
                float2 f = __half22float2(h2p[k]);
                accv[2*k]   += f.x * a;
                accv[2*k+1] += f.y * a;
            }
        }
    }
    // combine the four quarter-warps' accumulators
#pragma unroll
    for (int k = 0; k < 8; k++) {
        accv[k] += __shfl_xor_sync(0xFFFFFFFFu, accv[k], 8);
        accv[k] += __shfl_xor_sync(0xFFFFFFFFu, accv[k], 16);
    }
    // denom partials live in lanes 0..3
    den += __shfl_xor_sync(0xFFFFFFFFu, den, 1);
    den += __shfl_xor_sync(0xFFFFFFFFu, den, 2);
    den  = __shfl_sync(0xFFFFFFFFu, den, 0);
    const float inv = 1.f / (den + 1e-16f);
    float v[8];
    {
        const float4 b0 = ((const float4*)b2)[ql * 2];
        const float4 b1 = ((const float4*)b2)[ql * 2 + 1];
        v[0] = accv[0]*inv + b0.x; v[1] = accv[1]*inv + b0.y;
        v[2] = accv[2]*inv + b0.z; v[3] = accv[3]*inv + b0.w;
        v[4] = accv[4]*inv + b1.x; v[5] = accv[5]*inv + b1.y;
        v[6] = accv[6]*inv + b1.z; v[7] = accv[7]*inv + b1.w;
    }
    // log_softmax over the 64 row values (8 lanes x 8 values, groups identical)
    float mx = v[0];
#pragma unroll
    for (int k = 1; k < 8; k++) mx = fmaxf(mx, v[k]);
#pragma unroll
    for (int o = 1; o < 8; o <<= 1)
        mx = fmaxf(mx, __shfl_xor_sync(0xFFFFFFFFu, mx, o));
    float s = 0.f;
#pragma unroll
    for (int k = 0; k < 8; k++) s += expf(v[k] - mx);
#pragma unroll
    for (int o = 1; o < 8; o <<= 1)
        s += __shfl_xor_sync(0xFFFFFFFFu, s, o);
    const float lse = logf(s) + mx;
    if (grp == 0) {
        float4 o0 = make_float4(v[0]-lse, v[1]-lse, v[2]-lse, v[3]-lse);
        float4 o1 = make_float4(v[4]-lse, v[5]-lse, v[6]-lse, v[7]-lse);
        ((float4*)out)[n * 16 + ql * 2]     = o0;
        ((float4*)out)[n * 16 + ql * 2 + 1] = o1;
    }
}

extern "C" void kernel_launch(void* const* d_in, const int* in_sizes, int n_in,
                              void* d_out, int out_size) {
    const float* x   = (const float*)d_in[0];
    const void*  ei  = d_in[1];                 // int32 or int64, auto-detected
    const float* W1  = (const float*)d_in[2];
    const float* as1 = (const float*)d_in[3];
    const float* ad1 = (const float*)d_in[4];
    const float* b1  = (const float*)d_in[5];
    const float* W2  = (const float*)d_in[6];
    const float* as2 = (const float*)d_in[7];
    const float* ad2 = (const float*)d_in[8];
    const float* b2  = (const float*)d_in[9];
    float* out = (float*)d_out;

    const int warp_blocks = (N_NODES * 32 + 255) / 256;   // 6250

    init_k<<<SBLK, 512>>>(ei);
    fat1_k<<<GEMM_BLOCKS + DEC_BLOCKS, 512>>>(x, W1, ei);        // GEMM1 ∥ hist
    fat2_k<<<ALPHA1_BLOCKS + SBLK, 512>>>(as1, ad1);             // alpha1 ∥ scan-1
    midscan_k<<<1, 512>>>();
    emit_k<<<SBLK, 512>>>();
    scatter_k<<<(ET + 511) / 512, 512>>>(ei);
    agg1_k<<<warp_blocks, 256>>>();
    gemm2_k<<<GEMM_BLOCKS, 512>>>(W2, b1);
    alpha2_k<<<SBLK, 512>>>(as2, ad2);
    agg2_k<<<warp_blocks, 256>>>(out, b2);
}

// round 10
// speedup vs baseline: 2.1151x; 1.2709x over previous
#include <cuda_runtime.h>
#include <cuda_fp16.h>
#include <mma.h>

using namespace nvcuda;

// ---------------------------------------------------------------------------
// MultiGAT: 2-layer GAT on GB300.
// - GEMMs on fp16 tensor cores (wmma HMMA, fp32 accumulate); alpha logits
//   fused into GEMM epilogues from the pre-rounding fp32 accumulators.
// - Features h1/h2 stored fp16 (halves gather traffic); fp32 accumulation.
// - CSR gather-aggregate, no float atomics; softmax max-shift omitted
//   (mathematically identical ratio, values bounded).
// - edge_index dtype (int32 vs int64) auto-detected on device.
// ---------------------------------------------------------------------------

#define N_NODES 50000
#define NE      800000
#define ET      850000                    // NE + N_NODES self loops
#define GEMM_BLOCKS ((N_NODES + 127) / 128)     // 391
#define SBLK        ((N_NODES + 511) / 512)     // 98 scan blocks (512 thr)
#define DEC_BLOCKS  320                          // hist blocks appended to GEMM1

// -------- scratch (device globals; allocation-free) --------
__device__ __align__(16) __half g_h1h [N_NODES * 128];
__device__ __align__(16) float  g_agg1[N_NODES * 128];
__device__ __align__(16) __half g_h2h [N_NODES * 64];
__device__ float g_nas1[N_NODES * 8];
__device__ float g_nad1[N_NODES * 8];
__device__ float g_nas2[N_NODES];
__device__ float g_nad2[N_NODES];
__device__ int   g_esrc[ET];            // CSR: src per slot, grouped by dst
__device__ int   g_rowptr[N_NODES + 1];
__device__ int   g_woff[N_NODES];
__device__ int   g_cnt [N_NODES];
__device__ int   g_bsum[SBLK];
__device__ int   g_boff[SBLK];
__device__ int   g_is64;

__device__ __forceinline__ float eluf(float v) {
    return v > 0.f ? v : expm1f(v);
}

// -------- decode helpers --------
__device__ __forceinline__ int edge_dst(const void* ei, int e, int is64) {
    if (e >= NE) return e - NE;
    return is64 ? (int)((const long long*)ei)[NE + e] : ((const int*)ei)[NE + e];
}
__device__ __forceinline__ int edge_src(const void* ei, int e, int is64) {
    if (e >= NE) return e - NE;
    return is64 ? (int)((const long long*)ei)[e] : ((const int*)ei)[e];
}

// -------- init: zero histogram + dtype probe --------
__global__ void init_k(const void* __restrict__ ei) {
    int t = blockIdx.x * blockDim.x + threadIdx.x;
    if (t < N_NODES) g_cnt[t] = 0;
    if (t == 0) {
        const long long* p = (const long long*)ei;
        int ok = 1;
#pragma unroll 4
        for (int i = 0; i < 64; i++) {
            long long v = p[i];
            if (v < 0 || v >= N_NODES) ok = 0;
        }
        g_is64 = ok;
    }
}

// convert 8 fp32 (two float4) -> 16 halves into dst (16B-aligned)
__device__ __forceinline__ void cvt16(const float4 a, const float4 b,
                                      const float4 c, const float4 d,
                                      __half* dst) {
    __half2 h[8];
    h[0] = __floats2half2_rn(a.x, a.y); h[1] = __floats2half2_rn(a.z, a.w);
    h[2] = __floats2half2_rn(b.x, b.y); h[3] = __floats2half2_rn(b.z, b.w);
    h[4] = __floats2half2_rn(c.x, c.y); h[5] = __floats2half2_rn(c.z, c.w);
    h[6] = __floats2half2_rn(d.x, d.y); h[7] = __floats2half2_rn(d.z, d.w);
    ((uint4*)dst)[0] = ((uint4*)h)[0];
    ((uint4*)dst)[1] = ((uint4*)h)[1];
}

// ===========================================================================
// fat kernel 1: wmma GEMM1 (x@W1 -> fp16 h1 + alpha1) blocks + histogram
// block = 256 threads (8 warps: wm = wid&3 rows, wn = wid>>2 col-halves)
// ===========================================================================
#define AS_LD  80                         // half ld, As[128][80]
#define BS1_LD 136                        // half ld, Bs[64][136]
#define ST_LD  36                         // float ld, stage[128][36]

__global__ __launch_bounds__(256)
void fat1_k(const float* __restrict__ x, const float* __restrict__ W1,
            const float* __restrict__ as1, const float* __restrict__ ad1,
            const void* __restrict__ ei) {
    __shared__ __align__(16) char smem_raw[128 * AS_LD * 2 + 64 * BS1_LD * 2];
    if (blockIdx.x >= GEMM_BLOCKS) {
        const int is64 = g_is64;
        const int b = blockIdx.x - GEMM_BLOCKS;
        for (int e = b * 256 + threadIdx.x; e < ET; e += DEC_BLOCKS * 256)
            atomicAdd(&g_cnt[edge_dst(ei, e, is64)], 1);
        return;
    }
    __half* As = (__half*)smem_raw;                         // [128][AS_LD]
    __half* Bs = (__half*)(smem_raw + 128 * AS_LD * 2);     // [64][BS1_LD]
    float* stage = (float*)smem_raw;                        // [128][ST_LD] (reuse As)

    const int tid = threadIdx.x;
    const int wid = tid >> 5;
    const int wm = wid & 3, wn = wid >> 2;
    const int rowBase = blockIdx.x * 128;

    wmma::fragment<wmma::accumulator, 16, 16, 16, float> acc[2][4];
#pragma unroll
    for (int i = 0; i < 2; i++)
#pragma unroll
        for (int j = 0; j < 4; j++) wmma::fill_fragment(acc[i][j], 0.f);

    for (int kh = 0; kh < 2; kh++) {
        // A tile: 128 rows x 64 k (fp32 -> fp16)
        {
            const int r = tid >> 1, seg = tid & 1;
            const int row = rowBase + r;
            float4 v[8];
            if (row < N_NODES) {
                const float4* xp = (const float4*)(x + row * 128 + kh * 64 + seg * 32);
#pragma unroll
                for (int i = 0; i < 8; i++) v[i] = xp[i];
            } else {
#pragma unroll
                for (int i = 0; i < 8; i++) v[i] = make_float4(0.f, 0.f, 0.f, 0.f);
            }
            __half* dst = As + r * AS_LD + seg * 32;
            cvt16(v[0], v[1], v[2], v[3], dst);
            cvt16(v[4], v[5], v[6], v[7], dst + 16);
        }
        // B tile: 64 k x 128 n (fp32 -> fp16)
        {
            const int kk = tid >> 2, seg = tid & 3;
            const float4* wp = (const float4*)(W1 + (kh * 64 + kk) * 128 + seg * 32);
            float4 v[8];
#pragma unroll
            for (int i = 0; i < 8; i++) v[i] = wp[i];
            __half* dst = Bs + kk * BS1_LD + seg * 32;
            cvt16(v[0], v[1], v[2], v[3], dst);
            cvt16(v[4], v[5], v[6], v[7], dst + 16);
        }
        __syncthreads();
#pragma unroll
        for (int k8 = 0; k8 < 4; k8++) {
            wmma::fragment<wmma::matrix_a, 16, 16, 16, __half, wmma::row_major> af[2];
#pragma unroll
            for (int mi = 0; mi < 2; mi++)
                wmma::load_matrix_sync(af[mi], As + (wm * 32 + mi * 16) * AS_LD + k8 * 16, AS_LD);
#pragma unroll
            for (int nj = 0; nj < 4; nj++) {
                wmma::fragment<wmma::matrix_b, 16, 16, 16, __half, wmma::row_major> bf;
                wmma::load_matrix_sync(bf, Bs + (k8 * 16) * BS1_LD + wn * 64 + nj * 16, BS1_LD);
#pragma unroll
                for (int mi = 0; mi < 2; mi++)
                    wmma::mma_sync(acc[mi][nj], af[mi], bf, acc[mi][nj]);
            }
        }
        __syncthreads();
    }

    // epilogue: 4 column-quarters (32 cols each) staged through fp32 smem
    for (int q = 0; q < 4; q++) {
        if (wn == (q >> 1)) {
            const int njb = (q & 1) * 2;
#pragma unroll
            for (int mi = 0; mi < 2; mi++)
#pragma unroll
                for (int j = 0; j < 2; j++)
                    wmma::store_matrix_sync(stage + (wm * 32 + mi * 16) * ST_LD + j * 16,
                                            acc[mi][njb + j], ST_LD, wmma::mem_row_major);
        }
        __syncthreads();
        {
            const int r = tid >> 1, hf = tid & 1;
            const int row = rowBase + r;
            if (row < N_NODES) {
                const float* sp = stage + r * ST_LD + hf * 16;
                // fp16 store of 16 cols
                __half2 h[8];
#pragma unroll
                for (int i = 0; i < 8; i++)
                    h[i] = __floats2half2_rn(sp[2 * i], sp[2 * i + 1]);
                __half* dst = g_h1h + row * 128 + q * 32 + hf * 16;
                ((uint4*)dst)[0] = ((uint4*)h)[0];
                ((uint4*)dst)[1] = ((uint4*)h)[1];
                // alpha1 for head = q*2 + hf (head channels == this 16-col slice)
                const int head = q * 2 + hf;
                float s = 0.f, d = 0.f;
#pragma unroll
                for (int c = 0; c < 16; c++) {
                    s += sp[c] * as1[head * 16 + c];
                    d += sp[c] * ad1[head * 16 + c];
                }
                g_nas1[row * 8 + head] = s;
                g_nad1[row * 8 + head] = d;
            }
        }
        __syncthreads();
    }
}

// ===========================================================================
// wmma GEMM2: ELU(agg1+b1)@W2 -> fp16 h2 + alpha2 fused
// block = 256 threads (wm = wid&3 rows, wn = wid>>2 col-halves of 32)
// ===========================================================================
#define BS2_LD 80                         // half ld, Bs[64][80]

__global__ __launch_bounds__(256)
void gemm2_k(const float* __restrict__ W2, const float* __restrict__ b1,
             const float* __restrict__ as2, const float* __restrict__ ad2) {
    __shared__ __align__(16) char smem_raw[128 * AS_LD * 2 + 64 * BS2_LD * 2];
    __half* As = (__half*)smem_raw;                         // [128][AS_LD]
    __half* Bs = (__half*)(smem_raw + 128 * AS_LD * 2);     // [64][BS2_LD]
    float* stage = (float*)smem_raw;                        // [128][ST_LD]

    const int tid = threadIdx.x;
    const int wid = tid >> 5;
    const int wm = wid & 3, wn = wid >> 2;
    const int rowBase = blockIdx.x * 128;

    wmma::fragment<wmma::accumulator, 16, 16, 16, float> acc[2][2];
#pragma unroll
    for (int i = 0; i < 2; i++)
#pragma unroll
        for (int j = 0; j < 2; j++) wmma::fill_fragment(acc[i][j], 0.f);

    for (int kh = 0; kh < 2; kh++) {
        // A tile: ELU(agg1 + b1), fp32 -> fp16
        {
            const int r = tid >> 1, seg = tid & 1;
            const int row = rowBase + r;
            float4 v[8];
            if (row < N_NODES) {
                const float4* ap = (const float4*)(g_agg1 + row * 128 + kh * 64 + seg * 32);
                const float4* bp = (const float4*)(b1 + kh * 64 + seg * 32);
#pragma unroll
                for (int i = 0; i < 8; i++) {
                    float4 a = ap[i], b = bp[i];
                    v[i].x = eluf(a.x + b.x); v[i].y = eluf(a.y + b.y);
                    v[i].z = eluf(a.z + b.z); v[i].w = eluf(a.w + b.w);
                }
            } else {
#pragma unroll
                for (int i = 0; i < 8; i++) v[i] = make_float4(0.f, 0.f, 0.f, 0.f);
            }
            __half* dst = As + r * AS_LD + seg * 32;
            cvt16(v[0], v[1], v[2], v[3], dst);
            cvt16(v[4], v[5], v[6], v[7], dst + 16);
        }
        // B tile: 64 k x 64 n
        {
            const int kk = tid >> 2, seg = tid & 3;
            const float4* wp = (const float4*)(W2 + (kh * 64 + kk) * 64 + seg * 16);
            float4 v[4];
#pragma unroll
            for (int i = 0; i < 4; i++) v[i] = wp[i];
            __half* dst = Bs + kk * BS2_LD + seg * 16;
            cvt16(v[0], v[1], v[2], v[3], dst);
        }
        __syncthreads();
#pragma unroll
        for (int k8 = 0; k8 < 4; k8++) {
            wmma::fragment<wmma::matrix_a, 16, 16, 16, __half, wmma::row_major> af[2];
#pragma unroll
            for (int mi = 0; mi < 2; mi++)
                wmma::load_matrix_sync(af[mi], As + (wm * 32 + mi * 16) * AS_LD + k8 * 16, AS_LD);
#pragma unroll
            for (int nj = 0; nj < 2; nj++) {
                wmma::fragment<wmma::matrix_b, 16, 16, 16, __half, wmma::row_major> bf;
                wmma::load_matrix_sync(bf, Bs + (k8 * 16) * BS2_LD + wn * 32 + nj * 16, BS2_LD);
#pragma unroll
                for (int mi = 0; mi < 2; mi++)
                    wmma::mma_sync(acc[mi][nj], af[mi], bf, acc[mi][nj]);
            }
        }
        __syncthreads();
    }

    // epilogue: 2 column-quarters (32 cols each); alpha2 accumulated across both
    float s2 = 0.f, d2 = 0.f;                 // owned by threads tid<128 (row = tid)
    for (int q = 0; q < 2; q++) {
        if (wn == q) {
#pragma unroll
            for (int mi = 0; mi < 2; mi++)
#pragma unroll
                for (int j = 0; j < 2; j++)
                    wmma::store_matrix_sync(stage + (wm * 32 + mi * 16) * ST_LD + j * 16,
                                            acc[mi][j], ST_LD, wmma::mem_row_major);
        }
        __syncthreads();
        {
            const int r = tid >> 1, hf = tid & 1;
            const int row = rowBase + r;
            if (row < N_NODES) {
                const float* sp = stage + r * ST_LD + hf * 16;
                __half2 h[8];
#pragma unroll
                for (int i = 0; i < 8; i++)
                    h[i] = __floats2half2_rn(sp[2 * i], sp[2 * i + 1]);
                __half* dst = g_h2h + row * 64 + q * 32 + hf * 16;
                ((uint4*)dst)[0] = ((uint4*)h)[0];
                ((uint4*)dst)[1] = ((uint4*)h)[1];
            }
        }
        if (tid < 128) {
            const int row = rowBase + tid;
            if (row < N_NODES) {
                const float* sp = stage + tid * ST_LD;
#pragma unroll
                for (int c = 0; c < 32; c++) {
                    s2 += sp[c] * as2[q * 32 + c];
                    d2 += sp[c] * ad2[q * 32 + c];
                }
            }
        }
        __syncthreads();
    }
    if (tid < 128) {
        const int row = rowBase + tid;
        if (row < N_NODES) {
            g_nas2[row] = s2;
            g_nad2[row] = d2;
        }
    }
}

// -------- scan stage 1: per-block sums of g_cnt --------
__global__ void scan1_k() {
    __shared__ int wsum[16];
    const int t = threadIdx.x, lane = t & 31, w = t >> 5;
    const int i = blockIdx.x * 512 + t;
    int v = (i < N_NODES) ? g_cnt[i] : 0;
#pragma unroll
    for (int o = 16; o > 0; o >>= 1) v += __shfl_xor_sync(0xFFFFFFFFu, v, o);
    if (lane == 0) wsum[w] = v;
    __syncthreads();
    if (t == 0) {
        int s = 0;
#pragma unroll
        for (int k = 0; k < 16; k++) s += wsum[k];
        g_bsum[blockIdx.x] = s;
    }
}

// -------- scan stage 2: exclusive scan of SBLK block sums --------
__global__ void midscan_k() {
    __shared__ int wpre[16];
    const int t = threadIdx.x;                 // 512 threads
    const int lane = t & 31, w = t >> 5;
    int v = (t < SBLK) ? g_bsum[t] : 0;
    int inc = v;
#pragma unroll
    for (int o = 1; o < 32; o <<= 1) {
        int u = __shfl_up_sync(0xFFFFFFFFu, inc, o);
        if (lane >= o) inc += u;
    }
    if (lane == 31) wpre[w] = inc;
    __syncthreads();
    if (w == 0 && lane < 16) {
        int s = wpre[lane];
        int si = s;
#pragma unroll
        for (int o = 1; o < 16; o <<= 1) {
            int u = __shfl_up_sync(0xFFFFu, si, o);
            if (lane >= o) si += u;
        }
        wpre[lane] = si - s;   // exclusive warp offsets
    }
    __syncthreads();
    if (t < SBLK) g_boff[t] = inc - v + wpre[w];
    if (t == 0) g_rowptr[N_NODES] = ET;
}

// -------- scan stage 3: in-block exclusive scan + base offset --------
__global__ void emit_k() {
    __shared__ int wpre[16];
    const int t = threadIdx.x;                 // 512 threads
    const int lane = t & 31, w = t >> 5;
    const int i = blockIdx.x * 512 + t;
    int v = (i < N_NODES) ? g_cnt[i] : 0;
    int inc = v;
#pragma unroll
    for (int o = 1; o < 32; o <<= 1) {
        int u = __shfl_up_sync(0xFFFFFFFFu, inc, o);
        if (lane >= o) inc += u;
    }
    if (lane == 31) wpre[w] = inc;
    __syncthreads();
    if (t == 0) {
        int run = 0;
#pragma unroll
        for (int k = 0; k < 16; k++) { int u = wpre[k]; wpre[k] = run; run += u; }
    }
    __syncthreads();
    if (i < N_NODES) {
        const int ex = inc - v + wpre[w] + g_boff[blockIdx.x];
        g_rowptr[i] = ex;
        g_woff[i]   = ex;
    }
}

// -------- scatter edges into CSR slots (re-decode from edge_index) --------
__global__ void scatter_k(const void* __restrict__ ei) {
    int e = blockIdx.x * blockDim.x + threadIdx.x;
    if (e >= ET) return;
    const int is64 = g_is64;
    const int d = edge_dst(ei, e, is64);
    const int s = edge_src(ei, e, is64);
    int slot = atomicAdd(&g_woff[d], 1);
    g_esrc[slot] = s;
}

// -------- layer-1 aggregate: warp/node, fp16 gather, 4 edges/iter --------
// Row = 128 halves = 16 lanes x uint4; half-warp gathers one edge.
__global__ void agg1_k() {
    const int warp = (blockIdx.x * blockDim.x + threadIdx.x) >> 5;
    const int lane = threadIdx.x & 31;
    if (warp >= N_NODES) return;
    const int n = warp;
    const int rs = g_rowptr[n], re = g_rowptr[n + 1];
    const int ql  = lane & 15;         // channel group: owns channels ql*8..ql*8+7
    const int grp = lane >> 4;         // half-warp id (edge selector)
    const int hq  = ql >> 1;           // head of this lane's channels
    const float nadh = g_nad1[n * 8 + (lane & 7)];
    float den = 0.f;
    float accv[8];
#pragma unroll
    for (int k = 0; k < 8; k++) accv[k] = 0.f;

    for (int j = rs; j < re; j += 4) {
        const int eidx = j + (lane >> 3);   // lanes 8e..8e+7 handle edge j+e
        int srcg = 0;
        float ev = 0.f;
        if (eidx < re) {
            srcg = g_esrc[eidx];
            float v = g_nas1[srcg * 8 + (lane & 7)] + nadh;
            v = v > 0.f ? v : 0.2f * v;
            ev = __expf(v);
            den += ev;
        }
#pragma unroll
        for (int t = 0; t < 2; t++) {
            const int e0 = t * 2 + grp;     // this half-warp's edge this step
            // shuffles unconditional (warp-uniform execution)
            const int   src = __shfl_sync(0xFFFFFFFFu, srcg, e0 * 8);
            const float a   = __shfl_sync(0xFFFFFFFFu, ev,   e0 * 8 + hq);
            if (j + e0 < re) {
                uint4 raw = ((const uint4*)g_h1h)[src * 16 + ql];
                const __half2* h2p = (const __half2*)&raw;
#pragma unroll
                for (int k = 0; k < 4; k++) {
                    float2 f = __half22float2(h2p[k]);
                    accv[2*k]   += f.x * a;
                    accv[2*k+1] += f.y * a;
                }
            }
        }
    }
    // combine the two half-warps' accumulators
#pragma unroll
    for (int k = 0; k < 8; k++)
        accv[k] += __shfl_xor_sync(0xFFFFFFFFu, accv[k], 16);
    // per-head denom: partials for head h live in lanes {h, h+8, h+16, h+24}
    den += __shfl_xor_sync(0xFFFFFFFFu, den, 8);
    den += __shfl_xor_sync(0xFFFFFFFFu, den, 16);
    const float dh = __shfl_sync(0xFFFFFFFFu, den, hq);
    const float inv = 1.f / (dh + 1e-16f);
    if (grp == 0) {
        float4 o0 = make_float4(accv[0]*inv, accv[1]*inv, accv[2]*inv, accv[3]*inv);
        float4 o1 = make_float4(accv[4]*inv, accv[5]*inv, accv[6]*inv, accv[7]*inv);
        ((float4*)g_agg1)[n * 32 + ql * 2]     = o0;
        ((float4*)g_agg1)[n * 32 + ql * 2 + 1] = o1;
    }
}

// -------- layer-2 aggregate + bias + log_softmax: warp/node, 4 edges/iter ----
// Row = 64 halves = 8 lanes x uint4; quarter-warp gathers one edge.
__global__ void agg2_k(float* __restrict__ out, const float* __restrict__ b2) {
    const int warp = (blockIdx.x * blockDim.x + threadIdx.x) >> 5;
    const int lane = threadIdx.x & 31;
    if (warp >= N_NODES) return;
    const int n = warp;
    const int rs = g_rowptr[n], re = g_rowptr[n + 1];
    const int ql  = lane & 7;          // channel group: owns channels ql*8..ql*8+7
    const int grp = lane >> 3;         // quarter-warp id (edge selector, 0..3)
    const float nad = g_nad2[n];
    float den = 0.f;
    float accv[8];
#pragma unroll
    for (int k = 0; k < 8; k++) accv[k] = 0.f;

    for (int j = rs; j < re; j += 4) {
        const int idx = j + lane;
        int srcl = 0;
        float ev = 0.f;
        if (lane < 4 && idx < re) {
            srcl = g_esrc[idx];
            float v = g_nas2[srcl] + nad;
            v = v > 0.f ? v : 0.2f * v;
            ev = __expf(v);
            den += ev;
        }
        // each quarter-warp handles edge j+grp; shuffles unconditional
        const int   src = __shfl_sync(0xFFFFFFFFu, srcl, grp);
        const float a   = __shfl_sync(0xFFFFFFFFu, ev,   grp);
        if (j + grp < re) {
            uint4 raw = ((const uint4*)g_h2h)[src * 8 + ql];
            const __half2* h2p = (const __half2*)&raw;
#pragma unroll
            for (int k = 0; k < 4; k++) {
                float2 f = __half22float2(h2p[k]);
                accv[2*k]   += f.x * a;
                accv[2*k+1] += f.y * a;
            }
        }
    }
    // combine the four quarter-warps' accumulators
#pragma unroll
    for (int k = 0; k < 8; k++) {
        accv[k] += __shfl_xor_sync(0xFFFFFFFFu, accv[k], 8);
        accv[k] += __shfl_xor_sync(0xFFFFFFFFu, accv[k], 16);
    }
    // denom partials live in lanes 0..3
    den += __shfl_xor_sync(0xFFFFFFFFu, den, 1);
    den += __shfl_xor_sync(0xFFFFFFFFu, den, 2);
    den  = __shfl_sync(0xFFFFFFFFu, den, 0);
    const float inv = 1.f / (den + 1e-16f);
    float v[8];
    {
        const float4 b0 = ((const float4*)b2)[ql * 2];
        const float4 b1 = ((const float4*)b2)[ql * 2 + 1];
        v[0] = accv[0]*inv + b0.x; v[1] = accv[1]*inv + b0.y;
        v[2] = accv[2]*inv + b0.z; v[3] = accv[3]*inv + b0.w;
        v[4] = accv[4]*inv + b1.x; v[5] = accv[5]*inv + b1.y;
        v[6] = accv[6]*inv + b1.z; v[7] = accv[7]*inv + b1.w;
    }
    // log_softmax over the 64 row values (8 lanes x 8 values, groups identical)
    float mx = v[0];
#pragma unroll
    for (int k = 1; k < 8; k++) mx = fmaxf(mx, v[k]);
#pragma unroll
    for (int o = 1; o < 8; o <<= 1)
        mx = fmaxf(mx, __shfl_xor_sync(0xFFFFFFFFu, mx, o));
    float s = 0.f;
#pragma unroll
    for (int k = 0; k < 8; k++) s += expf(v[k] - mx);
#pragma unroll
    for (int o = 1; o < 8; o <<= 1)
        s += __shfl_xor_sync(0xFFFFFFFFu, s, o);
    const float lse = logf(s) + mx;
    if (grp == 0) {
        float4 o0 = make_float4(v[0]-lse, v[1]-lse, v[2]-lse, v[3]-lse);
        float4 o1 = make_float4(v[4]-lse, v[5]-lse, v[6]-lse, v[7]-lse);
        ((float4*)out)[n * 16 + ql * 2]     = o0;
        ((float4*)out)[n * 16 + ql * 2 + 1] = o1;
    }
}

extern "C" void kernel_launch(void* const* d_in, const int* in_sizes, int n_in,
                              void* d_out, int out_size) {
    const float* x   = (const float*)d_in[0];
    const void*  ei  = d_in[1];                 // int32 or int64, auto-detected
    const float* W1  = (const float*)d_in[2];
    const float* as1 = (const float*)d_in[3];
    const float* ad1 = (const float*)d_in[4];
    const float* b1  = (const float*)d_in[5];
    const float* W2  = (const float*)d_in[6];
    const float* as2 = (const float*)d_in[7];
    const float* ad2 = (const float*)d_in[8];
    const float* b2  = (const float*)d_in[9];
    float* out = (float*)d_out;

    const int warp_blocks = (N_NODES * 32 + 255) / 256;   // 6250

    init_k<<<SBLK, 512>>>(ei);
    fat1_k<<<GEMM_BLOCKS + DEC_BLOCKS, 256>>>(x, W1, as1, ad1, ei);  // GEMM1+alpha1 ∥ hist
    scan1_k<<<SBLK, 512>>>();
    midscan_k<<<1, 512>>>();
    emit_k<<<SBLK, 512>>>();
    scatter_k<<<(ET + 511) / 512, 512>>>(ei);
    agg1_k<<<warp_blocks, 256>>>();
    gemm2_k<<<GEMM_BLOCKS, 256>>>(W2, b1, as2, ad2);                 // GEMM2+alpha2
    agg2_k<<<warp_blocks, 256>>>(out, b2);
}

// round 11
// speedup vs baseline: 2.3174x; 1.0956x over previous
#include <cuda_runtime.h>
#include <cuda_fp16.h>
#include <mma.h>

using namespace nvcuda;

// ---------------------------------------------------------------------------
// MultiGAT: 2-layer GAT on GB300.
// - GEMMs on fp16 tensor cores (wmma HMMA, fp32 accumulate); alpha logits
//   fused into GEMM epilogues from the pre-rounding fp32 accumulators.
// - Features h1/h2 stored fp16; agg1 emits ELU(agg+b1) in fp16 so GEMM2's A
//   tile is a straight copy. fp32 accumulation everywhere.
// - CSR gather-aggregate (uint16 src ids), no float atomics; softmax
//   max-shift omitted (mathematically identical ratio, values bounded).
// - edge_index dtype (int32 vs int64) auto-detected on device.
// - 8-kernel serial chain; scan folded into 2 stages.
// ---------------------------------------------------------------------------

#define N_NODES 50000
#define NE      800000
#define ET      850000                    // NE + N_NODES self loops
#define GEMM_BLOCKS ((N_NODES + 127) / 128)     // 391
#define SBLK        ((N_NODES + 511) / 512)     // 98 scan blocks (512 thr)
#define DEC_BLOCKS  320                          // hist blocks appended to GEMM1

// -------- scratch (device globals; allocation-free) --------
__device__ __align__(16) __half g_h1h [N_NODES * 128];
__device__ __align__(16) __half g_agg1h[N_NODES * 128];   // ELU(agg1+b1), fp16
__device__ __align__(16) __half g_h2h [N_NODES * 64];
__device__ float g_nas1[N_NODES * 8];
__device__ float g_nad1[N_NODES * 8];
__device__ float g_nas2[N_NODES];
__device__ float g_nad2[N_NODES];
__device__ unsigned short g_esrc[ET];   // CSR: src per slot (node id < 65536)
__device__ int   g_rowptr[N_NODES + 1];
__device__ int   g_woff[N_NODES];
__device__ int   g_cnt [N_NODES];
__device__ int   g_bsum[SBLK];
__device__ int   g_is64;

__device__ __forceinline__ float eluf(float v) {
    return v > 0.f ? v : expm1f(v);
}

// -------- decode helpers --------
__device__ __forceinline__ int edge_dst(const void* ei, int e, int is64) {
    if (e >= NE) return e - NE;
    return is64 ? (int)((const long long*)ei)[NE + e] : ((const int*)ei)[NE + e];
}
__device__ __forceinline__ int edge_src(const void* ei, int e, int is64) {
    if (e >= NE) return e - NE;
    return is64 ? (int)((const long long*)ei)[e] : ((const int*)ei)[e];
}

// -------- init: zero histogram + dtype probe --------
__global__ void init_k(const void* __restrict__ ei) {
    int t = blockIdx.x * blockDim.x + threadIdx.x;
    if (t < N_NODES) g_cnt[t] = 0;
    if (t == 0) {
        const long long* p = (const long long*)ei;
        int ok = 1;
#pragma unroll 4
        for (int i = 0; i < 64; i++) {
            long long v = p[i];
            if (v < 0 || v >= N_NODES) ok = 0;
        }
        g_is64 = ok;
    }
}

// convert 8 fp32 (two float4) -> 16 halves into dst (16B-aligned)
__device__ __forceinline__ void cvt16(const float4 a, const float4 b,
                                      const float4 c, const float4 d,
                                      __half* dst) {
    __half2 h[8];
    h[0] = __floats2half2_rn(a.x, a.y); h[1] = __floats2half2_rn(a.z, a.w);
    h[2] = __floats2half2_rn(b.x, b.y); h[3] = __floats2half2_rn(b.z, b.w);
    h[4] = __floats2half2_rn(c.x, c.y); h[5] = __floats2half2_rn(c.z, c.w);
    h[6] = __floats2half2_rn(d.x, d.y); h[7] = __floats2half2_rn(d.z, d.w);
    ((uint4*)dst)[0] = ((uint4*)h)[0];
    ((uint4*)dst)[1] = ((uint4*)h)[1];
}

// ===========================================================================
// fat kernel 1: wmma GEMM1 (x@W1 -> fp16 h1 + alpha1) blocks + histogram
// block = 256 threads (8 warps: wm = wid&3 rows, wn = wid>>2 col-halves)
// ===========================================================================
#define AS_LD  80                         // half ld, As[128][80]
#define BS1_LD 136                        // half ld, Bs[64][136]
#define ST_LD  36                         // float ld, stage[128][36]

__global__ __launch_bounds__(256)
void fat1_k(const float* __restrict__ x, const float* __restrict__ W1,
            const float* __restrict__ as1, const float* __restrict__ ad1,
            const void* __restrict__ ei) {
    __shared__ __align__(16) char smem_raw[128 * AS_LD * 2 + 64 * BS1_LD * 2];
    if (blockIdx.x >= GEMM_BLOCKS) {
        const int is64 = g_is64;
        const int b = blockIdx.x - GEMM_BLOCKS;
        for (int e = b * 256 + threadIdx.x; e < ET; e += DEC_BLOCKS * 256)
            atomicAdd(&g_cnt[edge_dst(ei, e, is64)], 1);
        return;
    }
    __half* As = (__half*)smem_raw;                         // [128][AS_LD]
    __half* Bs = (__half*)(smem_raw + 128 * AS_LD * 2);     // [64][BS1_LD]
    float* stage = (float*)smem_raw;                        // [128][ST_LD] (reuse As)

    const int tid = threadIdx.x;
    const int wid = tid >> 5;
    const int wm = wid & 3, wn = wid >> 2;
    const int rowBase = blockIdx.x * 128;

    wmma::fragment<wmma::accumulator, 16, 16, 16, float> acc[2][4];
#pragma unroll
    for (int i = 0; i < 2; i++)
#pragma unroll
        for (int j = 0; j < 4; j++) wmma::fill_fragment(acc[i][j], 0.f);

    for (int kh = 0; kh < 2; kh++) {
        // A tile: 128 rows x 64 k (fp32 -> fp16)
        {
            const int r = tid >> 1, seg = tid & 1;
            const int row = rowBase + r;
            float4 v[8];
            if (row < N_NODES) {
                const float4* xp = (const float4*)(x + row * 128 + kh * 64 + seg * 32);
#pragma unroll
                for (int i = 0; i < 8; i++) v[i] = xp[i];
            } else {
#pragma unroll
                for (int i = 0; i < 8; i++) v[i] = make_float4(0.f, 0.f, 0.f, 0.f);
            }
            __half* dst = As + r * AS_LD + seg * 32;
            cvt16(v[0], v[1], v[2], v[3], dst);
            cvt16(v[4], v[5], v[6], v[7], dst + 16);
        }
        // B tile: 64 k x 128 n (fp32 -> fp16)
        {
            const int kk = tid >> 2, seg = tid & 3;
            const float4* wp = (const float4*)(W1 + (kh * 64 + kk) * 128 + seg * 32);
            float4 v[8];
#pragma unroll
            for (int i = 0; i < 8; i++) v[i] = wp[i];
            __half* dst = Bs + kk * BS1_LD + seg * 32;
            cvt16(v[0], v[1], v[2], v[3], dst);
            cvt16(v[4], v[5], v[6], v[7], dst + 16);
        }
        __syncthreads();
#pragma unroll
        for (int k8 = 0; k8 < 4; k8++) {
            wmma::fragment<wmma::matrix_a, 16, 16, 16, __half, wmma::row_major> af[2];
#pragma unroll
            for (int mi = 0; mi < 2; mi++)
                wmma::load_matrix_sync(af[mi], As + (wm * 32 + mi * 16) * AS_LD + k8 * 16, AS_LD);
#pragma unroll
            for (int nj = 0; nj < 4; nj++) {
                wmma::fragment<wmma::matrix_b, 16, 16, 16, __half, wmma::row_major> bf;
                wmma::load_matrix_sync(bf, Bs + (k8 * 16) * BS1_LD + wn * 64 + nj * 16, BS1_LD);
#pragma unroll
                for (int mi = 0; mi < 2; mi++)
                    wmma::mma_sync(acc[mi][nj], af[mi], bf, acc[mi][nj]);
            }
        }
        __syncthreads();
    }

    // epilogue: 4 column-quarters (32 cols each) staged through fp32 smem
    for (int q = 0; q < 4; q++) {
        if (wn == (q >> 1)) {
            const int njb = (q & 1) * 2;
#pragma unroll
            for (int mi = 0; mi < 2; mi++)
#pragma unroll
                for (int j = 0; j < 2; j++)
                    wmma::store_matrix_sync(stage + (wm * 32 + mi * 16) * ST_LD + j * 16,
                                            acc[mi][njb + j], ST_LD, wmma::mem_row_major);
        }
        __syncthreads();
        {
            const int r = tid >> 1, hf = tid & 1;
            const int row = rowBase + r;
            if (row < N_NODES) {
                const float* sp = stage + r * ST_LD + hf * 16;
                // fp16 store of 16 cols
                __half2 h[8];
#pragma unroll
                for (int i = 0; i < 8; i++)
                    h[i] = __floats2half2_rn(sp[2 * i], sp[2 * i + 1]);
                __half* dst = g_h1h + row * 128 + q * 32 + hf * 16;
                ((uint4*)dst)[0] = ((uint4*)h)[0];
                ((uint4*)dst)[1] = ((uint4*)h)[1];
                // alpha1 for head = q*2 + hf (head channels == this 16-col slice)
                const int head = q * 2 + hf;
                float s = 0.f, d = 0.f;
#pragma unroll
                for (int c = 0; c < 16; c++) {
                    s += sp[c] * as1[head * 16 + c];
                    d += sp[c] * ad1[head * 16 + c];
                }
                g_nas1[row * 8 + head] = s;
                g_nad1[row * 8 + head] = d;
            }
        }
        __syncthreads();
    }
}

// ===========================================================================
// wmma GEMM2: agg1h(fp16, already ELU(agg+b1)) @ W2 -> fp16 h2 + alpha2 fused
// block = 256 threads (wm = wid&3 rows, wn = wid>>2 col-halves of 32)
// ===========================================================================
#define BS2_LD 80                         // half ld, Bs[64][80]

__global__ __launch_bounds__(256)
void gemm2_k(const float* __restrict__ W2,
             const float* __restrict__ as2, const float* __restrict__ ad2) {
    __shared__ __align__(16) char smem_raw[128 * AS_LD * 2 + 64 * BS2_LD * 2];
    __half* As = (__half*)smem_raw;                         // [128][AS_LD]
    __half* Bs = (__half*)(smem_raw + 128 * AS_LD * 2);     // [64][BS2_LD]
    float* stage = (float*)smem_raw;                        // [128][ST_LD]

    const int tid = threadIdx.x;
    const int wid = tid >> 5;
    const int wm = wid & 3, wn = wid >> 2;
    const int rowBase = blockIdx.x * 128;

    wmma::fragment<wmma::accumulator, 16, 16, 16, float> acc[2][2];
#pragma unroll
    for (int i = 0; i < 2; i++)
#pragma unroll
        for (int j = 0; j < 2; j++) wmma::fill_fragment(acc[i][j], 0.f);

    for (int kh = 0; kh < 2; kh++) {
        // A tile: straight fp16 copy from g_agg1h
        {
            const int r = tid >> 1, seg = tid & 1;
            const int row = rowBase + r;
            uint4 v[4];
            if (row < N_NODES) {
                const uint4* ap = (const uint4*)(g_agg1h + row * 128 + kh * 64 + seg * 32);
#pragma unroll
                for (int i = 0; i < 4; i++) v[i] = ap[i];
            } else {
#pragma unroll
                for (int i = 0; i < 4; i++) v[i] = make_uint4(0u, 0u, 0u, 0u);
            }
            uint4* dst = (uint4*)(As + r * AS_LD + seg * 32);
#pragma unroll
            for (int i = 0; i < 4; i++) dst[i] = v[i];
        }
        // B tile: 64 k x 64 n (fp32 -> fp16)
        {
            const int kk = tid >> 2, seg = tid & 3;
            const float4* wp = (const float4*)(W2 + (kh * 64 + kk) * 64 + seg * 16);
            float4 v[4];
#pragma unroll
            for (int i = 0; i < 4; i++) v[i] = wp[i];
            __half* dst = Bs + kk * BS2_LD + seg * 16;
            cvt16(v[0], v[1], v[2], v[3], dst);
        }
        __syncthreads();
#pragma unroll
        for (int k8 = 0; k8 < 4; k8++) {
            wmma::fragment<wmma::matrix_a, 16, 16, 16, __half, wmma::row_major> af[2];
#pragma unroll
            for (int mi = 0; mi < 2; mi++)
                wmma::load_matrix_sync(af[mi], As + (wm * 32 + mi * 16) * AS_LD + k8 * 16, AS_LD);
#pragma unroll
            for (int nj = 0; nj < 2; nj++) {
                wmma::fragment<wmma::matrix_b, 16, 16, 16, __half, wmma::row_major> bf;
                wmma::load_matrix_sync(bf, Bs + (k8 * 16) * BS2_LD + wn * 32 + nj * 16, BS2_LD);
#pragma unroll
                for (int mi = 0; mi < 2; mi++)
                    wmma::mma_sync(acc[mi][nj], af[mi], bf, acc[mi][nj]);
            }
        }
        __syncthreads();
    }

    // epilogue: 2 column-quarters (32 cols each); alpha2 accumulated across both
    float s2 = 0.f, d2 = 0.f;                 // owned by threads tid<128 (row = tid)
    for (int q = 0; q < 2; q++) {
        if (wn == q) {
#pragma unroll
            for (int mi = 0; mi < 2; mi++)
#pragma unroll
                for (int j = 0; j < 2; j++)
                    wmma::store_matrix_sync(stage + (wm * 32 + mi * 16) * ST_LD + j * 16,
                                            acc[mi][j], ST_LD, wmma::mem_row_major);
        }
        __syncthreads();
        {
            const int r = tid >> 1, hf = tid & 1;
            const int row = rowBase + r;
            if (row < N_NODES) {
                const float* sp = stage + r * ST_LD + hf * 16;
                __half2 h[8];
#pragma unroll
                for (int i = 0; i < 8; i++)
                    h[i] = __floats2half2_rn(sp[2 * i], sp[2 * i + 1]);
                __half* dst = g_h2h + row * 64 + q * 32 + hf * 16;
                ((uint4*)dst)[0] = ((uint4*)h)[0];
                ((uint4*)dst)[1] = ((uint4*)h)[1];
            }
        }
        if (tid < 128) {
            const int row = rowBase + tid;
            if (row < N_NODES) {
                const float* sp = stage + tid * ST_LD;
#pragma unroll
                for (int c = 0; c < 32; c++) {
                    s2 += sp[c] * as2[q * 32 + c];
                    d2 += sp[c] * ad2[q * 32 + c];
                }
            }
        }
        __syncthreads();
    }
    if (tid < 128) {
        const int row = rowBase + tid;
        if (row < N_NODES) {
            g_nas2[row] = s2;
            g_nad2[row] = d2;
        }
    }
}

// -------- scan stage 1: per-block sums of g_cnt --------
__global__ void scan1_k() {
    __shared__ int wsum[16];
    const int t = threadIdx.x, lane = t & 31, w = t >> 5;
    const int i = blockIdx.x * 512 + t;
    int v = (i < N_NODES) ? g_cnt[i] : 0;
#pragma unroll
    for (int o = 16; o > 0; o >>= 1) v += __shfl_xor_sync(0xFFFFFFFFu, v, o);
    if (lane == 0) wsum[w] = v;
    __syncthreads();
    if (t == 0) {
        int s = 0;
#pragma unroll
        for (int k = 0; k < 16; k++) s += wsum[k];
        g_bsum[blockIdx.x] = s;
    }
}

// -------- scan stage 2 (fused): per-block base via in-block reduction of
//          g_bsum prefix + in-block exclusive scan -> rowptr/woff --------
__global__ void emit_k() {
    __shared__ int wpre[16];
    __shared__ int sbase;
    const int t = threadIdx.x;                 // 512 threads
    const int lane = t & 31, w = t >> 5;
    const int b = blockIdx.x;
    // base = sum of g_bsum[0..b-1]
    {
        int p = (t < b) ? g_bsum[t] : 0;       // b <= 98 < 512
#pragma unroll
        for (int o = 16; o > 0; o >>= 1) p += __shfl_xor_sync(0xFFFFFFFFu, p, o);
        if (lane == 0) wpre[w] = p;
        __syncthreads();
        if (t == 0) {
            int s = 0;
#pragma unroll
            for (int k = 0; k < 16; k++) s += wpre[k];
            sbase = s;
        }
        __syncthreads();
    }
    const int base = sbase;
    __syncthreads();                            // wpre about to be reused
    const int i = b * 512 + t;
    int v = (i < N_NODES) ? g_cnt[i] : 0;
    int inc = v;
#pragma unroll
    for (int o = 1; o < 32; o <<= 1) {
        int u = __shfl_up_sync(0xFFFFFFFFu, inc, o);
        if (lane >= o) inc += u;
    }
    if (lane == 31) wpre[w] = inc;
    __syncthreads();
    if (t == 0) {
        int run = 0;
#pragma unroll
        for (int k = 0; k < 16; k++) { int u = wpre[k]; wpre[k] = run; run += u; }
    }
    __syncthreads();
    if (i < N_NODES) {
        const int ex = inc - v + wpre[w] + base;
        g_rowptr[i] = ex;
        g_woff[i]   = ex;
    }
    if (b == 0 && t == 0) g_rowptr[N_NODES] = ET;
}

// -------- scatter edges into CSR slots (re-decode from edge_index) --------
__global__ void scatter_k(const void* __restrict__ ei) {
    int e = blockIdx.x * blockDim.x + threadIdx.x;
    if (e >= ET) return;
    const int is64 = g_is64;
    const int d = edge_dst(ei, e, is64);
    const int s = edge_src(ei, e, is64);
    int slot = atomicAdd(&g_woff[d], 1);
    g_esrc[slot] = (unsigned short)s;
}

// -------- layer-1 aggregate: warp/node, fp16 gather, 4 edges/iter;
//          emits ELU(acc/den + b1) in fp16 straight into GEMM2's A buffer ----
__global__ void agg1_k(const float* __restrict__ b1) {
    const int warp = (blockIdx.x * blockDim.x + threadIdx.x) >> 5;
    const int lane = threadIdx.x & 31;
    if (warp >= N_NODES) return;
    const int n = warp;
    const int rs = g_rowptr[n], re = g_rowptr[n + 1];
    const int ql  = lane & 15;         // channel group: owns channels ql*8..ql*8+7
    const int grp = lane >> 4;         // half-warp id (edge selector)
    const int hq  = ql >> 1;           // head of this lane's channels
    const float nadh = g_nad1[n * 8 + (lane & 7)];
    float den = 0.f;
    float accv[8];
#pragma unroll
    for (int k = 0; k < 8; k++) accv[k] = 0.f;

    for (int j = rs; j < re; j += 4) {
        const int eidx = j + (lane >> 3);   // lanes 8e..8e+7 handle edge j+e
        int srcg = 0;
        float ev = 0.f;
        if (eidx < re) {
            srcg = g_esrc[eidx];
            float v = g_nas1[srcg * 8 + (lane & 7)] + nadh;
            v = v > 0.f ? v : 0.2f * v;
            ev = __expf(v);
            den += ev;
        }
#pragma unroll
        for (int t = 0; t < 2; t++) {
            const int e0 = t * 2 + grp;     // this half-warp's edge this step
            // shuffles unconditional (warp-uniform execution)
            const int   src = __shfl_sync(0xFFFFFFFFu, srcg, e0 * 8);
            const float a   = __shfl_sync(0xFFFFFFFFu, ev,   e0 * 8 + hq);
            if (j + e0 < re) {
                uint4 raw = ((const uint4*)g_h1h)[src * 16 + ql];
                const __half2* h2p = (const __half2*)&raw;
#pragma unroll
                for (int k = 0; k < 4; k++) {
                    float2 f = __half22float2(h2p[k]);
                    accv[2*k]   += f.x * a;
                    accv[2*k+1] += f.y * a;
                }
            }
        }
    }
    // combine the two half-warps' accumulators
#pragma unroll
    for (int k = 0; k < 8; k++)
        accv[k] += __shfl_xor_sync(0xFFFFFFFFu, accv[k], 16);
    // per-head denom: partials for head h live in lanes {h, h+8, h+16, h+24}
    den += __shfl_xor_sync(0xFFFFFFFFu, den, 8);
    den += __shfl_xor_sync(0xFFFFFFFFu, den, 16);
    const float dh = __shfl_sync(0xFFFFFFFFu, den, hq);
    const float inv = 1.f / (dh + 1e-16f);
    if (grp == 0) {
        const float4 b0 = ((const float4*)b1)[ql * 2];
        const float4 b1v = ((const float4*)b1)[ql * 2 + 1];
        float o[8];
        o[0] = eluf(accv[0]*inv + b0.x); o[1] = eluf(accv[1]*inv + b0.y);
        o[2] = eluf(accv[2]*inv + b0.z); o[3] = eluf(accv[3]*inv + b0.w);
        o[4] = eluf(accv[4]*inv + b1v.x); o[5] = eluf(accv[5]*inv + b1v.y);
        o[6] = eluf(accv[6]*inv + b1v.z); o[7] = eluf(accv[7]*inv + b1v.w);
        __half2 h[4];
#pragma unroll
        for (int k = 0; k < 4; k++) h[k] = __floats2half2_rn(o[2*k], o[2*k+1]);
        ((uint4*)(g_agg1h + n * 128 + ql * 8))[0] = *(uint4*)h;
    }
}

// -------- layer-2 aggregate + bias + log_softmax: warp/node, 4 edges/iter ----
// Row = 64 halves = 8 lanes x uint4; quarter-warp gathers one edge.
__global__ void agg2_k(float* __restrict__ out, const float* __restrict__ b2) {
    const int warp = (blockIdx.x * blockDim.x + threadIdx.x) >> 5;
    const int lane = threadIdx.x & 31;
    if (warp >= N_NODES) return;
    const int n = warp;
    const int rs = g_rowptr[n], re = g_rowptr[n + 1];
    const int ql  = lane & 7;          // channel group: owns channels ql*8..ql*8+7
    const int grp = lane >> 3;         // quarter-warp id (edge selector, 0..3)
    const float nad = g_nad2[n];
    float den = 0.f;
    float accv[8];
#pragma unroll
    for (int k = 0; k < 8; k++) accv[k] = 0.f;

    for (int j = rs; j < re; j += 4) {
        const int idx = j + lane;
        int srcl = 0;
        float ev = 0.f;
        if (lane < 4 && idx < re) {
            srcl = g_esrc[idx];
            float v = g_nas2[srcl] + nad;
            v = v > 0.f ? v : 0.2f * v;
            ev = __expf(v);
            den += ev;
        }
        // each quarter-warp handles edge j+grp; shuffles unconditional
        const int   src = __shfl_sync(0xFFFFFFFFu, srcl, grp);
        const float a   = __shfl_sync(0xFFFFFFFFu, ev,   grp);
        if (j + grp < re) {
            uint4 raw = ((const uint4*)g_h2h)[src * 8 + ql];
            const __half2* h2p = (const __half2*)&raw;
#pragma unroll
            for (int k = 0; k < 4; k++) {
                float2 f = __half22float2(h2p[k]);
                accv[2*k]   += f.x * a;
                accv[2*k+1] += f.y * a;
            }
        }
    }
    // combine the four quarter-warps' accumulators
#pragma unroll
    for (int k = 0; k < 8; k++) {
        accv[k] += __shfl_xor_sync(0xFFFFFFFFu, accv[k], 8);
        accv[k] += __shfl_xor_sync(0xFFFFFFFFu, accv[k], 16);
    }
    // denom partials live in lanes 0..3
    den += __shfl_xor_sync(0xFFFFFFFFu, den, 1);
    den += __shfl_xor_sync(0xFFFFFFFFu, den, 2);
    den  = __shfl_sync(0xFFFFFFFFu, den, 0);
    const float inv = 1.f / (den + 1e-16f);
    float v[8];
    {
        const float4 b0 = ((const float4*)b2)[ql * 2];
        const float4 b1v = ((const float4*)b2)[ql * 2 + 1];
        v[0] = accv[0]*inv + b0.x; v[1] = accv[1]*inv + b0.y;
        v[2] = accv[2]*inv + b0.z; v[3] = accv[3]*inv + b0.w;
        v[4] = accv[4]*inv + b1v.x; v[5] = accv[5]*inv + b1v.y;
        v[6] = accv[6]*inv + b1v.z; v[7] = accv[7]*inv + b1v.w;
    }
    // log_softmax over the 64 row values (8 lanes x 8 values, groups identical)
    float mx = v[0];
#pragma unroll
    for (int k = 1; k < 8; k++) mx = fmaxf(mx, v[k]);
#pragma unroll
    for (int o = 1; o < 8; o <<= 1)
        mx = fmaxf(mx, __shfl_xor_sync(0xFFFFFFFFu, mx, o));
    float s = 0.f;
#pragma unroll
    for (int k = 0; k < 8; k++) s += expf(v[k] - mx);
#pragma unroll
    for (int o = 1; o < 8; o <<= 1)
        s += __shfl_xor_sync(0xFFFFFFFFu, s, o);
    const float lse = logf(s) + mx;
    if (grp == 0) {
        float4 o0 = make_float4(v[0]-lse, v[1]-lse, v[2]-lse, v[3]-lse);
        float4 o1 = make_float4(v[4]-lse, v[5]-lse, v[6]-lse, v[7]-lse);
        ((float4*)out)[n * 16 + ql * 2]     = o0;
        ((float4*)out)[n * 16 + ql * 2 + 1] = o1;
    }
}

extern "C" void kernel_launch(void* const* d_in, const int* in_sizes, int n_in,
                              void* d_out, int out_size) {
    const float* x   = (const float*)d_in[0];
    const void*  ei  = d_in[1];                 // int32 or int64, auto-detected
    const float* W1  = (const float*)d_in[2];
    const float* as1 = (const float*)d_in[3];
    const float* ad1 = (const float*)d_in[4];
    const float* b1  = (const float*)d_in[5];
    const float* W2  = (const float*)d_in[6];
    const float* as2 = (const float*)d_in[7];
    const float* ad2 = (const float*)d_in[8];
    const float* b2  = (const float*)d_in[9];
    float* out = (float*)d_out;

    const int warp_blocks = (N_NODES * 32 + 255) / 256;   // 6250

    init_k<<<SBLK, 512>>>(ei);
    fat1_k<<<GEMM_BLOCKS + DEC_BLOCKS, 256>>>(x, W1, as1, ad1, ei);  // GEMM1+alpha1 ∥ hist
    scan1_k<<<SBLK, 512>>>();
    emit_k<<<SBLK, 512>>>();                                          // scan + rowptr
    scatter_k<<<(ET + 511) / 512, 512>>>(ei);
    agg1_k<<<warp_blocks, 256>>>(b1);
    gemm2_k<<<GEMM_BLOCKS, 256>>>(W2, as2, ad2);                      // GEMM2+alpha2
    agg2_k<<<warp_blocks, 256>>>(out, b2);
}

// round 13
// speedup vs baseline: 2.3179x; 1.0002x over previous
#include <cuda_runtime.h>
#include <cuda_fp16.h>
#include <mma.h>

using namespace nvcuda;

// ---------------------------------------------------------------------------
// MultiGAT: 2-layer GAT on GB300.
// - GEMMs on fp16 tensor cores (wmma HMMA, fp32 accumulate); alpha logits
//   fused into GEMM epilogues from the pre-rounding fp32 accumulators.
// - Features h1/h2 stored fp16; agg1 emits ELU(agg+b1) in fp16 so GEMM2's A
//   tile is a straight copy. fp32 accumulation everywhere.
// - CSR gather-aggregate (uint16 src ids), no float atomics; softmax
//   max-shift omitted (mathematically identical ratio, values bounded).
// - edge_index dtype (int32 vs int64) detected by inline 32-byte probe.
// - 6-kernel chain: fat1(GEMM1+alpha1 ∥ hist) -> lookback-scan -> scatter ->
//   agg1 -> gemm2(+alpha2) -> agg2. Scan statuses reset by scatter; g_cnt
//   zeroed by the scan kernel after use (globals start zeroed).
// - R11 fix: lookback status words are UNSIGNED (2<<30 overflowed signed int;
//   arithmetic >> made the PREFIX status unreadable -> spin deadlock).
// ---------------------------------------------------------------------------

#define N_NODES 50000
#define NE      800000
#define ET      850000                    // NE + N_NODES self loops
#define GEMM_BLOCKS ((N_NODES + 127) / 128)     // 391
#define SBLK        ((N_NODES + 511) / 512)     // 98 scan blocks (512 thr)
#define DEC_BLOCKS  320                          // hist blocks appended to GEMM1

// -------- scratch (device globals; allocation-free) --------
__device__ __align__(16) __half g_h1h [N_NODES * 128];
__device__ __align__(16) __half g_agg1h[N_NODES * 128];   // ELU(agg1+b1), fp16
__device__ __align__(16) __half g_h2h [N_NODES * 64];
__device__ float g_nas1[N_NODES * 8];
__device__ float g_nad1[N_NODES * 8];
__device__ float g_nas2[N_NODES];
__device__ float g_nad2[N_NODES];
__device__ unsigned short g_esrc[ET];   // CSR: src per slot (node id < 65536)
__device__ int   g_rowptr[N_NODES + 1];
__device__ int   g_woff[N_NODES];
__device__ int   g_cnt [N_NODES];       // zeroed at load; re-zeroed by scan_k
__device__ unsigned int g_scan[SBLK];   // packed lookback word; reset by scatter_k

__device__ __forceinline__ float eluf(float v) {
    return v > 0.f ? v : expm1f(v);
}

// -------- dtype probe: int64 iff the first 8 high words are all zero --------
// (int64 indices in [0,N) have zero high words; int32 random indices hit zero
//  w.p. 2e-5 per slot -> false-64 prob ~1e-37). 32 bytes, L1-cached.
__device__ __forceinline__ int probe64(const void* ei) {
    const int2* p = (const int2*)ei;
    int ok = 1;
#pragma unroll
    for (int i = 0; i < 8; i++) ok &= (p[i].y == 0);
    return ok;
}

// -------- decode helpers --------
__device__ __forceinline__ int edge_dst(const void* ei, int e, int is64) {
    if (e >= NE) return e - NE;
    return is64 ? (int)((const long long*)ei)[NE + e] : ((const int*)ei)[NE + e];
}
__device__ __forceinline__ int edge_src(const void* ei, int e, int is64) {
    if (e >= NE) return e - NE;
    return is64 ? (int)((const long long*)ei)[e] : ((const int*)ei)[e];
}

// convert 8 fp32 (two float4) -> 16 halves into dst (16B-aligned)
__device__ __forceinline__ void cvt16(const float4 a, const float4 b,
                                      const float4 c, const float4 d,
                                      __half* dst) {
    __half2 h[8];
    h[0] = __floats2half2_rn(a.x, a.y); h[1] = __floats2half2_rn(a.z, a.w);
    h[2] = __floats2half2_rn(b.x, b.y); h[3] = __floats2half2_rn(b.z, b.w);
    h[4] = __floats2half2_rn(c.x, c.y); h[5] = __floats2half2_rn(c.z, c.w);
    h[6] = __floats2half2_rn(d.x, d.y); h[7] = __floats2half2_rn(d.z, d.w);
    ((uint4*)dst)[0] = ((uint4*)h)[0];
    ((uint4*)dst)[1] = ((uint4*)h)[1];
}

// ===========================================================================
// fat kernel 1: wmma GEMM1 (x@W1 -> fp16 h1 + alpha1) blocks + histogram
// block = 256 threads (8 warps: wm = wid&3 rows, wn = wid>>2 col-halves)
// ===========================================================================
#define AS_LD  80                         // half ld, As[128][80]
#define BS1_LD 136                        // half ld, Bs[64][136]
#define ST_LD  36                         // float ld, stage[128][36]

__global__ __launch_bounds__(256)
void fat1_k(const float* __restrict__ x, const float* __restrict__ W1,
            const float* __restrict__ as1, const float* __restrict__ ad1,
            const void* __restrict__ ei) {
    __shared__ __align__(16) char smem_raw[128 * AS_LD * 2 + 64 * BS1_LD * 2];
    if (blockIdx.x >= GEMM_BLOCKS) {
        const int is64 = probe64(ei);
        const int b = blockIdx.x - GEMM_BLOCKS;
        for (int e = b * 256 + threadIdx.x; e < ET; e += DEC_BLOCKS * 256)
            atomicAdd(&g_cnt[edge_dst(ei, e, is64)], 1);
        return;
    }
    __half* As = (__half*)smem_raw;                         // [128][AS_LD]
    __half* Bs = (__half*)(smem_raw + 128 * AS_LD * 2);     // [64][BS1_LD]
    float* stage = (float*)smem_raw;                        // [128][ST_LD] (reuse As)

    const int tid = threadIdx.x;
    const int wid = tid >> 5;
    const int wm = wid & 3, wn = wid >> 2;
    const int rowBase = blockIdx.x * 128;

    wmma::fragment<wmma::accumulator, 16, 16, 16, float> acc[2][4];
#pragma unroll
    for (int i = 0; i < 2; i++)
#pragma unroll
        for (int j = 0; j < 4; j++) wmma::fill_fragment(acc[i][j], 0.f);

    for (int kh = 0; kh < 2; kh++) {
        // A tile: 128 rows x 64 k (fp32 -> fp16)
        {
            const int r = tid >> 1, seg = tid & 1;
            const int row = rowBase + r;
            float4 v[8];
            if (row < N_NODES) {
                const float4* xp = (const float4*)(x + row * 128 + kh * 64 + seg * 32);
#pragma unroll
                for (int i = 0; i < 8; i++) v[i] = xp[i];
            } else {
#pragma unroll
                for (int i = 0; i < 8; i++) v[i] = make_float4(0.f, 0.f, 0.f, 0.f);
            }
            __half* dst = As + r * AS_LD + seg * 32;
            cvt16(v[0], v[1], v[2], v[3], dst);
            cvt16(v[4], v[5], v[6], v[7], dst + 16);
        }
        // B tile: 64 k x 128 n (fp32 -> fp16)
        {
            const int kk = tid >> 2, seg = tid & 3;
            const float4* wp = (const float4*)(W1 + (kh * 64 + kk) * 128 + seg * 32);
            float4 v[8];
#pragma unroll
            for (int i = 0; i < 8; i++) v[i] = wp[i];
            __half* dst = Bs + kk * BS1_LD + seg * 32;
            cvt16(v[0], v[1], v[2], v[3], dst);
            cvt16(v[4], v[5], v[6], v[7], dst + 16);
        }
        __syncthreads();
#pragma unroll
        for (int k8 = 0; k8 < 4; k8++) {
            wmma::fragment<wmma::matrix_a, 16, 16, 16, __half, wmma::row_major> af[2];
#pragma unroll
            for (int mi = 0; mi < 2; mi++)
                wmma::load_matrix_sync(af[mi], As + (wm * 32 + mi * 16) * AS_LD + k8 * 16, AS_LD);
#pragma unroll
            for (int nj = 0; nj < 4; nj++) {
                wmma::fragment<wmma::matrix_b, 16, 16, 16, __half, wmma::row_major> bf;
                wmma::load_matrix_sync(bf, Bs + (k8 * 16) * BS1_LD + wn * 64 + nj * 16, BS1_LD);
#pragma unroll
                for (int mi = 0; mi < 2; mi++)
                    wmma::mma_sync(acc[mi][nj], af[mi], bf, acc[mi][nj]);
            }
        }
        __syncthreads();
    }

    // epilogue: 4 column-quarters (32 cols each) staged through fp32 smem
    for (int q = 0; q < 4; q++) {
        if (wn == (q >> 1)) {
            const int njb = (q & 1) * 2;
#pragma unroll
            for (int mi = 0; mi < 2; mi++)
#pragma unroll
                for (int j = 0; j < 2; j++)
                    wmma::store_matrix_sync(stage + (wm * 32 + mi * 16) * ST_LD + j * 16,
                                            acc[mi][njb + j], ST_LD, wmma::mem_row_major);
        }
        __syncthreads();
        {
            const int r = tid >> 1, hf = tid & 1;
            const int row = rowBase + r;
            if (row < N_NODES) {
                const float* sp = stage + r * ST_LD + hf * 16;
                // fp16 store of 16 cols
                __half2 h[8];
#pragma unroll
                for (int i = 0; i < 8; i++)
                    h[i] = __floats2half2_rn(sp[2 * i], sp[2 * i + 1]);
                __half* dst = g_h1h + row * 128 + q * 32 + hf * 16;
                ((uint4*)dst)[0] = ((uint4*)h)[0];
                ((uint4*)dst)[1] = ((uint4*)h)[1];
                // alpha1 for head = q*2 + hf (head channels == this 16-col slice)
                const int head = q * 2 + hf;
                float s = 0.f, d = 0.f;
#pragma unroll
                for (int c = 0; c < 16; c++) {
                    s += sp[c] * as1[head * 16 + c];
                    d += sp[c] * ad1[head * 16 + c];
                }
                g_nas1[row * 8 + head] = s;
                g_nad1[row * 8 + head] = d;
            }
        }
        __syncthreads();
    }
}

// ===========================================================================
// decoupled-lookback scan: g_cnt -> rowptr/woff in ONE kernel (98 blocks,
// single wave on 148 SMs -> no residency deadlock). Packed UNSIGNED word per
// block: bits[30:32)=status (0 none / 1 aggregate / 2 prefix), bits[0:30)=
// value (ET < 2^30). Logical shifts on unsigned decode correctly.
// g_cnt is zeroed after use (ready for next graph replay).
// ===========================================================================
__global__ void scan_k() {
    __shared__ int wpre[16];
    __shared__ int sbase;
    const int t = threadIdx.x;                 // 512 threads
    const int lane = t & 31, w = t >> 5;
    const int b = blockIdx.x;
    const int i = b * 512 + t;
    int v = (i < N_NODES) ? g_cnt[i] : 0;
    int inc = v;
#pragma unroll
    for (int o = 1; o < 32; o <<= 1) {
        int u = __shfl_up_sync(0xFFFFFFFFu, inc, o);
        if (lane >= o) inc += u;
    }
    if (lane == 31) wpre[w] = inc;
    __syncthreads();
    if (t == 0) {
        int run = 0;
#pragma unroll
        for (int k = 0; k < 16; k++) { int u = wpre[k]; wpre[k] = run; run += u; }
        // run = this block's total
        int base = 0;
        if (b == 0) {
            atomicExch(&g_scan[0], (2u << 30) | (unsigned)run);
        } else {
            atomicExch(&g_scan[b], (1u << 30) | (unsigned)run);  // publish aggregate
            int idx = b - 1;
            while (true) {
                unsigned int word;
                do { word = atomicAdd(&g_scan[idx], 0u); } while ((word >> 30) == 0u);
                base += (int)(word & 0x3FFFFFFFu);
                if ((word >> 30) == 2u) break;
                idx--;
            }
            atomicExch(&g_scan[b], (2u << 30) | (unsigned)(base + run));  // prefix
        }
        sbase = base;
    }
    __syncthreads();
    if (i < N_NODES) {
        const int ex = inc - v + wpre[w] + sbase;
        g_rowptr[i] = ex;
        g_woff[i]   = ex;
        g_cnt[i]    = 0;                        // ready for next replay
    }
    if (b == 0 && t == 0) g_rowptr[N_NODES] = ET;
}

// -------- scatter edges into CSR slots (re-decode from edge_index);
//          also resets the lookback words for the next replay --------
__global__ void scatter_k(const void* __restrict__ ei) {
    int e = blockIdx.x * blockDim.x + threadIdx.x;
    if (e < SBLK) g_scan[e] = 0u;
    if (e >= ET) return;
    const int is64 = probe64(ei);
    const int d = edge_dst(ei, e, is64);
    const int s = edge_src(ei, e, is64);
    int slot = atomicAdd(&g_woff[d], 1);
    g_esrc[slot] = (unsigned short)s;
}

// -------- layer-1 aggregate: warp/node, fp16 gather, 4 edges/iter;
//          emits ELU(acc/den + b1) in fp16 straight into GEMM2's A buffer ----
__global__ void agg1_k(const float* __restrict__ b1) {
    const int warp = (blockIdx.x * blockDim.x + threadIdx.x) >> 5;
    const int lane = threadIdx.x & 31;
    if (warp >= N_NODES) return;
    const int n = warp;
    const int rs = g_rowptr[n], re = g_rowptr[n + 1];
    const int ql  = lane & 15;         // channel group: owns channels ql*8..ql*8+7
    const int grp = lane >> 4;         // half-warp id (edge selector)
    const int hq  = ql >> 1;           // head of this lane's channels
    const float nadh = g_nad1[n * 8 + (lane & 7)];
    float den = 0.f;
    float accv[8];
#pragma unroll
    for (int k = 0; k < 8; k++) accv[k] = 0.f;

    for (int j = rs; j < re; j += 4) {
        const int eidx = j + (lane >> 3);   // lanes 8e..8e+7 handle edge j+e
        int srcg = 0;
        float ev = 0.f;
        if (eidx < re) {
            srcg = g_esrc[eidx];
            float v = g_nas1[srcg * 8 + (lane & 7)] + nadh;
            v = v > 0.f ? v : 0.2f * v;
            ev = __expf(v);
            den += ev;
        }
#pragma unroll
        for (int t = 0; t < 2; t++) {
            const int e0 = t * 2 + grp;     // this half-warp's edge this step
            // shuffles unconditional (warp-uniform execution)
            const int   src = __shfl_sync(0xFFFFFFFFu, srcg, e0 * 8);
            const float a   = __shfl_sync(0xFFFFFFFFu, ev,   e0 * 8 + hq);
            if (j + e0 < re) {
                uint4 raw = ((const uint4*)g_h1h)[src * 16 + ql];
                const __half2* h2p = (const __half2*)&raw;
#pragma unroll
                for (int k = 0; k < 4; k++) {
                    float2 f = __half22float2(h2p[k]);
                    accv[2*k]   += f.x * a;
                    accv[2*k+1] += f.y * a;
                }
            }
        }
    }
    // combine the two half-warps' accumulators
#pragma unroll
    for (int k = 0; k < 8; k++)
        accv[k] += __shfl_xor_sync(0xFFFFFFFFu, accv[k], 16);
    // per-head denom: partials for head h live in lanes {h, h+8, h+16, h+24}
    den += __shfl_xor_sync(0xFFFFFFFFu, den, 8);
    den += __shfl_xor_sync(0xFFFFFFFFu, den, 16);
    const float dh = __shfl_sync(0xFFFFFFFFu, den, hq);
    const float inv = 1.f / (dh + 1e-16f);
    if (grp == 0) {
        const float4 b0 = ((const float4*)b1)[ql * 2];
        const float4 b1v = ((const float4*)b1)[ql * 2 + 1];
        float o[8];
        o[0] = eluf(accv[0]*inv + b0.x); o[1] = eluf(accv[1]*inv + b0.y);
        o[2] = eluf(accv[2]*inv + b0.z); o[3] = eluf(accv[3]*inv + b0.w);
        o[4] = eluf(accv[4]*inv + b1v.x); o[5] = eluf(accv[5]*inv + b1v.y);
        o[6] = eluf(accv[6]*inv + b1v.z); o[7] = eluf(accv[7]*inv + b1v.w);
        __half2 h[4];
#pragma unroll
        for (int k = 0; k < 4; k++) h[k] = __floats2half2_rn(o[2*k], o[2*k+1]);
        ((uint4*)(g_agg1h + n * 128 + ql * 8))[0] = *(uint4*)h;
    }
}

// ===========================================================================
// wmma GEMM2: agg1h(fp16, already ELU(agg+b1)) @ W2 -> fp16 h2 + alpha2 fused
// block = 256 threads (wm = wid&3 rows, wn = wid>>2 col-halves of 32)
// ===========================================================================
#define BS2_LD 80                         // half ld, Bs[64][80]

__global__ __launch_bounds__(256)
void gemm2_k(const float* __restrict__ W2,
             const float* __restrict__ as2, const float* __restrict__ ad2) {
    __shared__ __align__(16) char smem_raw[128 * AS_LD * 2 + 64 * BS2_LD * 2];
    __half* As = (__half*)smem_raw;                         // [128][AS_LD]
    __half* Bs = (__half*)(smem_raw + 128 * AS_LD * 2);     // [64][BS2_LD]
    float* stage = (float*)smem_raw;                        // [128][ST_LD]

    const int tid = threadIdx.x;
    const int wid = tid >> 5;
    const int wm = wid & 3, wn = wid >> 2;
    const int rowBase = blockIdx.x * 128;

    wmma::fragment<wmma::accumulator, 16, 16, 16, float> acc[2][2];
#pragma unroll
    for (int i = 0; i < 2; i++)
#pragma unroll
        for (int j = 0; j < 2; j++) wmma::fill_fragment(acc[i][j], 0.f);

    for (int kh = 0; kh < 2; kh++) {
        // A tile: straight fp16 copy from g_agg1h
        {
            const int r = tid >> 1, seg = tid & 1;
            const int row = rowBase + r;
            uint4 v[4];
            if (row < N_NODES) {
                const uint4* ap = (const uint4*)(g_agg1h + row * 128 + kh * 64 + seg * 32);
#pragma unroll
                for (int i = 0; i < 4; i++) v[i] = ap[i];
            } else {
#pragma unroll
                for (int i = 0; i < 4; i++) v[i] = make_uint4(0u, 0u, 0u, 0u);
            }
            uint4* dst = (uint4*)(As + r * AS_LD + seg * 32);
#pragma unroll
            for (int i = 0; i < 4; i++) dst[i] = v[i];
        }
        // B tile: 64 k x 64 n (fp32 -> fp16)
        {
            const int kk = tid >> 2, seg = tid & 3;
            const float4* wp = (const float4*)(W2 + (kh * 64 + kk) * 64 + seg * 16);
            float4 v[4];
#pragma unroll
            for (int i = 0; i < 4; i++) v[i] = wp[i];
            __half* dst = Bs + kk * BS2_LD + seg * 16;
            cvt16(v[0], v[1], v[2], v[3], dst);
        }
        __syncthreads();
#pragma unroll
        for (int k8 = 0; k8 < 4; k8++) {
            wmma::fragment<wmma::matrix_a, 16, 16, 16, __half, wmma::row_major> af[2];
#pragma unroll
            for (int mi = 0; mi < 2; mi++)
                wmma::load_matrix_sync(af[mi], As + (wm * 32 + mi * 16) * AS_LD + k8 * 16, AS_LD);
#pragma unroll
            for (int nj = 0; nj < 2; nj++) {
                wmma::fragment<wmma::matrix_b, 16, 16, 16, __half, wmma::row_major> bf;
                wmma::load_matrix_sync(bf, Bs + (k8 * 16) * BS2_LD + wn * 32 + nj * 16, BS2_LD);
#pragma unroll
                for (int mi = 0; mi < 2; mi++)
                    wmma::mma_sync(acc[mi][nj], af[mi], bf, acc[mi][nj]);
            }
        }
        __syncthreads();
    }

    // epilogue: 2 column-quarters (32 cols each); alpha2 accumulated across both
    float s2 = 0.f, d2 = 0.f;                 // owned by threads tid<128 (row = tid)
    for (int q = 0; q < 2; q++) {
        if (wn == q) {
#pragma unroll
            for (int mi = 0; mi < 2; mi++)
#pragma unroll
                for (int j = 0; j < 2; j++)
                    wmma::store_matrix_sync(stage + (wm * 32 + mi * 16) * ST_LD + j * 16,
                                            acc[mi][j], ST_LD, wmma::mem_row_major);
        }
        __syncthreads();
        {
            const int r = tid >> 1, hf = tid & 1;
            const int row = rowBase + r;
            if (row < N_NODES) {
                const float* sp = stage + r * ST_LD + hf * 16;
                __half2 h[8];
#pragma unroll
                for (int i = 0; i < 8; i++)
                    h[i] = __floats2half2_rn(sp[2 * i], sp[2 * i + 1]);
                __half* dst = g_h2h + row * 64 + q * 32 + hf * 16;
                ((uint4*)dst)[0] = ((uint4*)h)[0];
                ((uint4*)dst)[1] = ((uint4*)h)[1];
            }
        }
        if (tid < 128) {
            const int row = rowBase + tid;
            if (row < N_NODES) {
                const float* sp = stage + tid * ST_LD;
#pragma unroll
                for (int c = 0; c < 32; c++) {
                    s2 += sp[c] * as2[q * 32 + c];
                    d2 += sp[c] * ad2[q * 32 + c];
                }
            }
        }
        __syncthreads();
    }
    if (tid < 128) {
        const int row = rowBase + tid;
        if (row < N_NODES) {
            g_nas2[row] = s2;
            g_nad2[row] = d2;
        }
    }
}

// -------- layer-2 aggregate + bias + log_softmax: warp/node, 4 edges/iter ----
// Row = 64 halves = 8 lanes x uint4; quarter-warp gathers one edge.
__global__ void agg2_k(float* __restrict__ out, const float* __restrict__ b2) {
    const int warp = (blockIdx.x * blockDim.x + threadIdx.x) >> 5;
    const int lane = threadIdx.x & 31;
    if (warp >= N_NODES) return;
    const int n = warp;
    const int rs = g_rowptr[n], re = g_rowptr[n + 1];
    const int ql  = lane & 7;          // channel group: owns channels ql*8..ql*8+7
    const int grp = lane >> 3;         // quarter-warp id (edge selector, 0..3)
    const float nad = g_nad2[n];
    float den = 0.f;
    float accv[8];
#pragma unroll
    for (int k = 0; k < 8; k++) accv[k] = 0.f;

    for (int j = rs; j < re; j += 4) {
        const int idx = j + lane;
        int srcl = 0;
        float ev = 0.f;
        if (lane < 4 && idx < re) {
            srcl = g_esrc[idx];
            float v = g_nas2[srcl] + nad;
            v = v > 0.f ? v : 0.2f * v;
            ev = __expf(v);
            den += ev;
        }
        // each quarter-warp handles edge j+grp; shuffles unconditional
        const int   src = __shfl_sync(0xFFFFFFFFu, srcl, grp);
        const float a   = __shfl_sync(0xFFFFFFFFu, ev,   grp);
        if (j + grp < re) {
            uint4 raw = ((const uint4*)g_h2h)[src * 8 + ql];
            const __half2* h2p = (const __half2*)&raw;
#pragma unroll
            for (int k = 0; k < 4; k++) {
                float2 f = __half22float2(h2p[k]);
                accv[2*k]   += f.x * a;
                accv[2*k+1] += f.y * a;
            }
        }
    }
    // combine the four quarter-warps' accumulators
#pragma unroll
    for (int k = 0; k < 8; k++) {
        accv[k] += __shfl_xor_sync(0xFFFFFFFFu, accv[k], 8);
        accv[k] += __shfl_xor_sync(0xFFFFFFFFu, accv[k], 16);
    }
    // denom partials live in lanes 0..3
    den += __shfl_xor_sync(0xFFFFFFFFu, den, 1);
    den += __shfl_xor_sync(0xFFFFFFFFu, den, 2);
    den  = __shfl_sync(0xFFFFFFFFu, den, 0);
    const float inv = 1.f / (den + 1e-16f);
    float v[8];
    {
        const float4 b0 = ((const float4*)b2)[ql * 2];
        const float4 b1v = ((const float4*)b2)[ql * 2 + 1];
        v[0] = accv[0]*inv + b0.x; v[1] = accv[1]*inv + b0.y;
        v[2] = accv[2]*inv + b0.z; v[3] = accv[3]*inv + b0.w;
        v[4] = accv[4]*inv + b1v.x; v[5] = accv[5]*inv + b1v.y;
        v[6] = accv[6]*inv + b1v.z; v[7] = accv[7]*inv + b1v.w;
    }
    // log_softmax over the 64 row values (8 lanes x 8 values, groups identical)
    float mx = v[0];
#pragma unroll
    for (int k = 1; k < 8; k++) mx = fmaxf(mx, v[k]);
#pragma unroll
    for (int o = 1; o < 8; o <<= 1)
        mx = fmaxf(mx, __shfl_xor_sync(0xFFFFFFFFu, mx, o));
    float s = 0.f;
#pragma unroll
    for (int k = 0; k < 8; k++) s += expf(v[k] - mx);
#pragma unroll
    for (int o = 1; o < 8; o <<= 1)
        s += __shfl_xor_sync(0xFFFFFFFFu, s, o);
    const float lse = logf(s) + mx;
    if (grp == 0) {
        float4 o0 = make_float4(v[0]-lse, v[1]-lse, v[2]-lse, v[3]-lse);
        float4 o1 = make_float4(v[4]-lse, v[5]-lse, v[6]-lse, v[7]-lse);
        ((float4*)out)[n * 16 + ql * 2]     = o0;
        ((float4*)out)[n * 16 + ql * 2 + 1] = o1;
    }
}

extern "C" void kernel_launch(void* const* d_in, const int* in_sizes, int n_in,
                              void* d_out, int out_size) {
    const float* x   = (const float*)d_in[0];
    const void*  ei  = d_in[1];                 // int32 or int64, probed inline
    const float* W1  = (const float*)d_in[2];
    const float* as1 = (const float*)d_in[3];
    const float* ad1 = (const float*)d_in[4];
    const float* b1  = (const float*)d_in[5];
    const float* W2  = (const float*)d_in[6];
    const float* as2 = (const float*)d_in[7];
    const float* ad2 = (const float*)d_in[8];
    const float* b2  = (const float*)d_in[9];
    float* out = (float*)d_out;

    const int warp_blocks = (N_NODES * 32 + 255) / 256;   // 6250

    fat1_k<<<GEMM_BLOCKS + DEC_BLOCKS, 256>>>(x, W1, as1, ad1, ei);  // GEMM1+alpha1 ∥ hist
    scan_k<<<SBLK, 512>>>();                                          // lookback scan
    scatter_k<<<(ET + 511) / 512, 512>>>(ei);
    agg1_k<<<warp_blocks, 256>>>(b1);
    gemm2_k<<<GEMM_BLOCKS, 256>>>(W2, as2, ad2);                      // GEMM2+alpha2
    agg2_k<<<warp_blocks, 256>>>(out, b2);
}

// round 14
// speedup vs baseline: 2.4028x; 1.0366x over previous
#include <cuda_runtime.h>
#include <cuda_fp16.h>
#include <mma.h>

using namespace nvcuda;

// ---------------------------------------------------------------------------
// MultiGAT: 2-layer GAT on GB300.
// - GEMMs on fp16 tensor cores (wmma HMMA, fp32 accumulate); alpha logits
//   fused into GEMM epilogues from the pre-rounding fp32 accumulators.
// - Features h1/h2 stored fp16; agg1 emits ELU(agg+b1) in fp16 so GEMM2's A
//   tile is a straight copy.
// - agg1 accumulates in packed __half2 (HFMA2) — it is ISSUE-bound, not
//   memory-bound (ncu R12: alu 40% / fma 30% / L2 19%); errors at this stage
//   attenuate ~50x through GEMM2+softmax (measured R8->R9). agg2 stays fp32.
// - CSR gather-aggregate (uint16 src ids), no float atomics; softmax
//   max-shift omitted (mathematically identical ratio, values bounded).
// - edge_index dtype (int32 vs int64) detected by inline 32-byte probe.
// - 6-kernel chain: fat1(GEMM1+alpha1 ∥ hist) -> lookback-scan -> scatter ->
//   agg1 -> gemm2(+alpha2) -> agg2. Self-cleaning scratch for graph replay.
// ---------------------------------------------------------------------------

#define N_NODES 50000
#define NE      800000
#define ET      850000                    // NE + N_NODES self loops
#define GEMM_BLOCKS ((N_NODES + 127) / 128)     // 391
#define SBLK        ((N_NODES + 511) / 512)     // 98 scan blocks (512 thr)
#define DEC_BLOCKS  320                          // hist blocks appended to GEMM1

// -------- scratch (device globals; allocation-free) --------
__device__ __align__(16) __half g_h1h [N_NODES * 128];
__device__ __align__(16) __half g_agg1h[N_NODES * 128];   // ELU(agg1+b1), fp16
__device__ __align__(16) __half g_h2h [N_NODES * 64];
__device__ float g_nas1[N_NODES * 8];
__device__ float g_nad1[N_NODES * 8];
__device__ float g_nas2[N_NODES];
__device__ float g_nad2[N_NODES];
__device__ unsigned short g_esrc[ET];   // CSR: src per slot (node id < 65536)
__device__ int   g_rowptr[N_NODES + 1];
__device__ int   g_woff[N_NODES];
__device__ int   g_cnt [N_NODES];       // zeroed at load; re-zeroed by scan_k
__device__ unsigned int g_scan[SBLK];   // packed lookback word; reset by scatter_k

__device__ __forceinline__ float eluf(float v) {
    return v > 0.f ? v : expm1f(v);
}

// -------- dtype probe: int64 iff the first 8 high words are all zero --------
__device__ __forceinline__ int probe64(const void* ei) {
    const int2* p = (const int2*)ei;
    int ok = 1;
#pragma unroll
    for (int i = 0; i < 8; i++) ok &= (p[i].y == 0);
    return ok;
}

// -------- decode helpers --------
__device__ __forceinline__ int edge_dst(const void* ei, int e, int is64) {
    if (e >= NE) return e - NE;
    return is64 ? (int)((const long long*)ei)[NE + e] : ((const int*)ei)[NE + e];
}
__device__ __forceinline__ int edge_src(const void* ei, int e, int is64) {
    if (e >= NE) return e - NE;
    return is64 ? (int)((const long long*)ei)[e] : ((const int*)ei)[e];
}

// convert 8 fp32 (two float4) -> 16 halves into dst (16B-aligned)
__device__ __forceinline__ void cvt16(const float4 a, const float4 b,
                                      const float4 c, const float4 d,
                                      __half* dst) {
    __half2 h[8];
    h[0] = __floats2half2_rn(a.x, a.y); h[1] = __floats2half2_rn(a.z, a.w);
    h[2] = __floats2half2_rn(b.x, b.y); h[3] = __floats2half2_rn(b.z, b.w);
    h[4] = __floats2half2_rn(c.x, c.y); h[5] = __floats2half2_rn(c.z, c.w);
    h[6] = __floats2half2_rn(d.x, d.y); h[7] = __floats2half2_rn(d.z, d.w);
    ((uint4*)dst)[0] = ((uint4*)h)[0];
    ((uint4*)dst)[1] = ((uint4*)h)[1];
}

// ===========================================================================
// fat kernel 1: wmma GEMM1 (x@W1 -> fp16 h1 + alpha1) blocks + histogram
// ===========================================================================
#define AS_LD  80                         // half ld, As[128][80]
#define BS1_LD 136                        // half ld, Bs[64][136]
#define ST_LD  36                         // float ld, stage[128][36]

__global__ __launch_bounds__(256)
void fat1_k(const float* __restrict__ x, const float* __restrict__ W1,
            const float* __restrict__ as1, const float* __restrict__ ad1,
            const void* __restrict__ ei) {
    __shared__ __align__(16) char smem_raw[128 * AS_LD * 2 + 64 * BS1_LD * 2];
    if (blockIdx.x >= GEMM_BLOCKS) {
        const int is64 = probe64(ei);
        const int b = blockIdx.x - GEMM_BLOCKS;
        for (int e = b * 256 + threadIdx.x; e < ET; e += DEC_BLOCKS * 256)
            atomicAdd(&g_cnt[edge_dst(ei, e, is64)], 1);
        return;
    }
    __half* As = (__half*)smem_raw;                         // [128][AS_LD]
    __half* Bs = (__half*)(smem_raw + 128 * AS_LD * 2);     // [64][BS1_LD]
    float* stage = (float*)smem_raw;                        // [128][ST_LD] (reuse As)

    const int tid = threadIdx.x;
    const int wid = tid >> 5;
    const int wm = wid & 3, wn = wid >> 2;
    const int rowBase = blockIdx.x * 128;

    wmma::fragment<wmma::accumulator, 16, 16, 16, float> acc[2][4];
#pragma unroll
    for (int i = 0; i < 2; i++)
#pragma unroll
        for (int j = 0; j < 4; j++) wmma::fill_fragment(acc[i][j], 0.f);

    for (int kh = 0; kh < 2; kh++) {
        // A tile: 128 rows x 64 k (fp32 -> fp16)
        {
            const int r = tid >> 1, seg = tid & 1;
            const int row = rowBase + r;
            float4 v[8];
            if (row < N_NODES) {
                const float4* xp = (const float4*)(x + row * 128 + kh * 64 + seg * 32);
#pragma unroll
                for (int i = 0; i < 8; i++) v[i] = xp[i];
            } else {
#pragma unroll
                for (int i = 0; i < 8; i++) v[i] = make_float4(0.f, 0.f, 0.f, 0.f);
            }
            __half* dst = As + r * AS_LD + seg * 32;
            cvt16(v[0], v[1], v[2], v[3], dst);
            cvt16(v[4], v[5], v[6], v[7], dst + 16);
        }
        // B tile: 64 k x 128 n (fp32 -> fp16)
        {
            const int kk = tid >> 2, seg = tid & 3;
            const float4* wp = (const float4*)(W1 + (kh * 64 + kk) * 128 + seg * 32);
            float4 v[8];
#pragma unroll
            for (int i = 0; i < 8; i++) v[i] = wp[i];
            __half* dst = Bs + kk * BS1_LD + seg * 32;
            cvt16(v[0], v[1], v[2], v[3], dst);
            cvt16(v[4], v[5], v[6], v[7], dst + 16);
        }
        __syncthreads();
#pragma unroll
        for (int k8 = 0; k8 < 4; k8++) {
            wmma::fragment<wmma::matrix_a, 16, 16, 16, __half, wmma::row_major> af[2];
#pragma unroll
            for (int mi = 0; mi < 2; mi++)
                wmma::load_matrix_sync(af[mi], As + (wm * 32 + mi * 16) * AS_LD + k8 * 16, AS_LD);
#pragma unroll
            for (int nj = 0; nj < 4; nj++) {
                wmma::fragment<wmma::matrix_b, 16, 16, 16, __half, wmma::row_major> bf;
                wmma::load_matrix_sync(bf, Bs + (k8 * 16) * BS1_LD + wn * 64 + nj * 16, BS1_LD);
#pragma unroll
                for (int mi = 0; mi < 2; mi++)
                    wmma::mma_sync(acc[mi][nj], af[mi], bf, acc[mi][nj]);
            }
        }
        __syncthreads();
    }

    // epilogue: 4 column-quarters (32 cols each) staged through fp32 smem
    for (int q = 0; q < 4; q++) {
        if (wn == (q >> 1)) {
            const int njb = (q & 1) * 2;
#pragma unroll
            for (int mi = 0; mi < 2; mi++)
#pragma unroll
                for (int j = 0; j < 2; j++)
                    wmma::store_matrix_sync(stage + (wm * 32 + mi * 16) * ST_LD + j * 16,
                                            acc[mi][njb + j], ST_LD, wmma::mem_row_major);
        }
        __syncthreads();
        {
            const int r = tid >> 1, hf = tid & 1;
            const int row = rowBase + r;
            if (row < N_NODES) {
                const float* sp = stage + r * ST_LD + hf * 16;
                __half2 h[8];
#pragma unroll
                for (int i = 0; i < 8; i++)
                    h[i] = __floats2half2_rn(sp[2 * i], sp[2 * i + 1]);
                __half* dst = g_h1h + row * 128 + q * 32 + hf * 16;
                ((uint4*)dst)[0] = ((uint4*)h)[0];
                ((uint4*)dst)[1] = ((uint4*)h)[1];
                const int head = q * 2 + hf;
                float s = 0.f, d = 0.f;
#pragma unroll
                for (int c = 0; c < 16; c++) {
                    s += sp[c] * as1[head * 16 + c];
                    d += sp[c] * ad1[head * 16 + c];
                }
                g_nas1[row * 8 + head] = s;
                g_nad1[row * 8 + head] = d;
            }
        }
        __syncthreads();
    }
}

// ===========================================================================
// decoupled-lookback scan (unsigned status words): g_cnt -> rowptr/woff
// ===========================================================================
__global__ void scan_k() {
    __shared__ int wpre[16];
    __shared__ int sbase;
    const int t = threadIdx.x;                 // 512 threads
    const int lane = t & 31, w = t >> 5;
    const int b = blockIdx.x;
    const int i = b * 512 + t;
    int v = (i < N_NODES) ? g_cnt[i] : 0;
    int inc = v;
#pragma unroll
    for (int o = 1; o < 32; o <<= 1) {
        int u = __shfl_up_sync(0xFFFFFFFFu, inc, o);
        if (lane >= o) inc += u;
    }
    if (lane == 31) wpre[w] = inc;
    __syncthreads();
    if (t == 0) {
        int run = 0;
#pragma unroll
        for (int k = 0; k < 16; k++) { int u = wpre[k]; wpre[k] = run; run += u; }
        int base = 0;
        if (b == 0) {
            atomicExch(&g_scan[0], (2u << 30) | (unsigned)run);
        } else {
            atomicExch(&g_scan[b], (1u << 30) | (unsigned)run);  // publish aggregate
            int idx = b - 1;
            while (true) {
                unsigned int word;
                do { word = atomicAdd(&g_scan[idx], 0u); } while ((word >> 30) == 0u);
                base += (int)(word & 0x3FFFFFFFu);
                if ((word >> 30) == 2u) break;
                idx--;
            }
            atomicExch(&g_scan[b], (2u << 30) | (unsigned)(base + run));  // prefix
        }
        sbase = base;
    }
    __syncthreads();
    if (i < N_NODES) {
        const int ex = inc - v + wpre[w] + sbase;
        g_rowptr[i] = ex;
        g_woff[i]   = ex;
        g_cnt[i]    = 0;                        // ready for next replay
    }
    if (b == 0 && t == 0) g_rowptr[N_NODES] = ET;
}

// -------- scatter edges into CSR slots; resets lookback words --------
__global__ void scatter_k(const void* __restrict__ ei) {
    int e = blockIdx.x * blockDim.x + threadIdx.x;
    if (e < SBLK) g_scan[e] = 0u;
    if (e >= ET) return;
    const int is64 = probe64(ei);
    const int d = edge_dst(ei, e, is64);
    const int s = edge_src(ei, e, is64);
    int slot = atomicAdd(&g_woff[d], 1);
    g_esrc[slot] = (unsigned short)s;
}

// -------- layer-1 aggregate: warp/node, fp16 gather, 4 edges/iter;
//          HFMA2 half2 accumulation (issue-bound kernel; errors attenuate
//          ~50x downstream); emits ELU(acc/den + b1) in fp16 --------
__global__ void agg1_k(const float* __restrict__ b1) {
    const int warp = (blockIdx.x * blockDim.x + threadIdx.x) >> 5;
    const int lane = threadIdx.x & 31;
    if (warp >= N_NODES) return;
    const int n = warp;
    const int rs = g_rowptr[n], re = g_rowptr[n + 1];
    const int ql  = lane & 15;         // channel group: owns channels ql*8..ql*8+7
    const int grp = lane >> 4;         // half-warp id (edge selector)
    const int hq  = ql >> 1;           // head of this lane's channels
    const float nadh = g_nad1[n * 8 + (lane & 7)];
    float den = 0.f;
    __half2 hacc[4];
#pragma unroll
    for (int k = 0; k < 4; k++) hacc[k] = __float2half2_rn(0.f);

    for (int j = rs; j < re; j += 4) {
        const int eidx = j + (lane >> 3);   // lanes 8e..8e+7 handle edge j+e
        int srcg = 0;
        float ev = 0.f;
        if (eidx < re) {
            srcg = g_esrc[eidx];
            float v = g_nas1[srcg * 8 + (lane & 7)] + nadh;
            v = v > 0.f ? v : 0.2f * v;
            ev = __expf(v);
            den += ev;
        }
#pragma unroll
        for (int t = 0; t < 2; t++) {
            const int e0 = t * 2 + grp;     // this half-warp's edge this step
            // shuffles unconditional (warp-uniform execution)
            const int   src = __shfl_sync(0xFFFFFFFFu, srcg, e0 * 8);
            const float a   = __shfl_sync(0xFFFFFFFFu, ev,   e0 * 8 + hq);
            if (j + e0 < re) {
                const __half2 a2 = __float2half2_rn(a);
                uint4 raw = ((const uint4*)g_h1h)[src * 16 + ql];
                const __half2* h2p = (const __half2*)&raw;
#pragma unroll
                for (int k = 0; k < 4; k++)
                    hacc[k] = __hfma2(h2p[k], a2, hacc[k]);
            }
        }
    }
    // unpack to fp32 and combine the two half-warps' accumulators
    float accv[8];
#pragma unroll
    for (int k = 0; k < 4; k++) {
        float2 f = __half22float2(hacc[k]);
        accv[2*k]   = f.x;
        accv[2*k+1] = f.y;
    }
#pragma unroll
    for (int k = 0; k < 8; k++)
        accv[k] += __shfl_xor_sync(0xFFFFFFFFu, accv[k], 16);
    // per-head denom: partials for head h live in lanes {h, h+8, h+16, h+24}
    den += __shfl_xor_sync(0xFFFFFFFFu, den, 8);
    den += __shfl_xor_sync(0xFFFFFFFFu, den, 16);
    const float dh = __shfl_sync(0xFFFFFFFFu, den, hq);
    const float inv = 1.f / (dh + 1e-16f);
    if (grp == 0) {
        const float4 b0 = ((const float4*)b1)[ql * 2];
        const float4 b1v = ((const float4*)b1)[ql * 2 + 1];
        float o[8];
        o[0] = eluf(accv[0]*inv + b0.x); o[1] = eluf(accv[1]*inv + b0.y);
        o[2] = eluf(accv[2]*inv + b0.z); o[3] = eluf(accv[3]*inv + b0.w);
        o[4] = eluf(accv[4]*inv + b1v.x); o[5] = eluf(accv[5]*inv + b1v.y);
        o[6] = eluf(accv[6]*inv + b1v.z); o[7] = eluf(accv[7]*inv + b1v.w);
        __half2 h[4];
#pragma unroll
        for (int k = 0; k < 4; k++) h[k] = __floats2half2_rn(o[2*k], o[2*k+1]);
        ((uint4*)(g_agg1h + n * 128 + ql * 8))[0] = *(uint4*)h;
    }
}

// ===========================================================================
// wmma GEMM2: agg1h(fp16, already ELU(agg+b1)) @ W2 -> fp16 h2 + alpha2 fused
// ===========================================================================
#define BS2_LD 80                         // half ld, Bs[64][80]

__global__ __launch_bounds__(256)
void gemm2_k(const float* __restrict__ W2,
             const float* __restrict__ as2, const float* __restrict__ ad2) {
    __shared__ __align__(16) char smem_raw[128 * AS_LD * 2 + 64 * BS2_LD * 2];
    __half* As = (__half*)smem_raw;                         // [128][AS_LD]
    __half* Bs = (__half*)(smem_raw + 128 * AS_LD * 2);     // [64][BS2_LD]
    float* stage = (float*)smem_raw;                        // [128][ST_LD]

    const int tid = threadIdx.x;
    const int wid = tid >> 5;
    const int wm = wid & 3, wn = wid >> 2;
    const int rowBase = blockIdx.x * 128;

    wmma::fragment<wmma::accumulator, 16, 16, 16, float> acc[2][2];
#pragma unroll
    for (int i = 0; i < 2; i++)
#pragma unroll
        for (int j = 0; j < 2; j++) wmma::fill_fragment(acc[i][j], 0.f);

    for (int kh = 0; kh < 2; kh++) {
        // A tile: straight fp16 copy from g_agg1h
        {
            const int r = tid >> 1, seg = tid & 1;
            const int row = rowBase + r;
            uint4 v[4];
            if (row < N_NODES) {
                const uint4* ap = (const uint4*)(g_agg1h + row * 128 + kh * 64 + seg * 32);
#pragma unroll
                for (int i = 0; i < 4; i++) v[i] = ap[i];
            } else {
#pragma unroll
                for (int i = 0; i < 4; i++) v[i] = make_uint4(0u, 0u, 0u, 0u);
            }
            uint4* dst = (uint4*)(As + r * AS_LD + seg * 32);
#pragma unroll
            for (int i = 0; i < 4; i++) dst[i] = v[i];
        }
        // B tile: 64 k x 64 n (fp32 -> fp16)
        {
            const int kk = tid >> 2, seg = tid & 3;
            const float4* wp = (const float4*)(W2 + (kh * 64 + kk) * 64 + seg * 16);
            float4 v[4];
#pragma unroll
            for (int i = 0; i < 4; i++) v[i] = wp[i];
            __half* dst = Bs + kk * BS2_LD + seg * 16;
            cvt16(v[0], v[1], v[2], v[3], dst);
        }
        __syncthreads();
#pragma unroll
        for (int k8 = 0; k8 < 4; k8++) {
            wmma::fragment<wmma::matrix_a, 16, 16, 16, __half, wmma::row_major> af[2];
#pragma unroll
            for (int mi = 0; mi < 2; mi++)
                wmma::load_matrix_sync(af[mi], As + (wm * 32 + mi * 16) * AS_LD + k8 * 16, AS_LD);
#pragma unroll
            for (int nj = 0; nj < 2; nj++) {
                wmma::fragment<wmma::matrix_b, 16, 16, 16, __half, wmma::row_major> bf;
                wmma::load_matrix_sync(bf, Bs + (k8 * 16) * BS2_LD + wn * 32 + nj * 16, BS2_LD);
#pragma unroll
                for (int mi = 0; mi < 2; mi++)
                    wmma::mma_sync(acc[mi][nj], af[mi], bf, acc[mi][nj]);
            }
        }
        __syncthreads();
    }

    // epilogue: 2 column-quarters (32 cols each); alpha2 accumulated across both
    float s2 = 0.f, d2 = 0.f;                 // owned by threads tid<128 (row = tid)
    for (int q = 0; q < 2; q++) {
        if (wn == q) {
#pragma unroll
            for (int mi = 0; mi < 2; mi++)
#pragma unroll
                for (int j = 0; j < 2; j++)
                    wmma::store_matrix_sync(stage + (wm * 32 + mi * 16) * ST_LD + j * 16,
                                            acc[mi][j], ST_LD, wmma::mem_row_major);
        }
        __syncthreads();
        {
            const int r = tid >> 1, hf = tid & 1;
            const int row = rowBase + r;
            if (row < N_NODES) {
                const float* sp = stage + r * ST_LD + hf * 16;
                __half2 h[8];
#pragma unroll
                for (int i = 0; i < 8; i++)
                    h[i] = __floats2half2_rn(sp[2 * i], sp[2 * i + 1]);
                __half* dst = g_h2h + row * 64 + q * 32 + hf * 16;
                ((uint4*)dst)[0] = ((uint4*)h)[0];
                ((uint4*)dst)[1] = ((uint4*)h)[1];
            }
        }
        if (tid < 128) {
            const int row = rowBase + tid;
            if (row < N_NODES) {
                const float* sp = stage + tid * ST_LD;
#pragma unroll
                for (int c = 0; c < 32; c++) {
                    s2 += sp[c] * as2[q * 32 + c];
                    d2 += sp[c] * ad2[q * 32 + c];
                }
            }
        }
        __syncthreads();
    }
    if (tid < 128) {
        const int row = rowBase + tid;
        if (row < N_NODES) {
            g_nas2[row] = s2;
            g_nad2[row] = d2;
        }
    }
}

// -------- layer-2 aggregate + bias + log_softmax: warp/node, 4 edges/iter ----
__global__ void agg2_k(float* __restrict__ out, const float* __restrict__ b2) {
    const int warp = (blockIdx.x * blockDim.x + threadIdx.x) >> 5;
    const int lane = threadIdx.x & 31;
    if (warp >= N_NODES) return;
    const int n = warp;
    const int rs = g_rowptr[n], re = g_rowptr[n + 1];
    const int ql  = lane & 7;          // channel group: owns channels ql*8..ql*8+7
    const int grp = lane >> 3;         // quarter-warp id (edge selector, 0..3)
    const float nad = g_nad2[n];
    float den = 0.f;
    float accv[8];
#pragma unroll
    for (int k = 0; k < 8; k++) accv[k] = 0.f;

    for (int j = rs; j < re; j += 4) {
        const int idx = j + lane;
        int srcl = 0;
        float ev = 0.f;
        if (lane < 4 && idx < re) {
            srcl = g_esrc[idx];
            float v = g_nas2[srcl] + nad;
            v = v > 0.f ? v : 0.2f * v;
            ev = __expf(v);
            den += ev;
        }
        // each quarter-warp handles edge j+grp; shuffles unconditional
        const int   src = __shfl_sync(0xFFFFFFFFu, srcl, grp);
        const float a   = __shfl_sync(0xFFFFFFFFu, ev,   grp);
        if (j + grp < re) {
            uint4 raw = ((const uint4*)g_h2h)[src * 8 + ql];
            const __half2* h2p = (const __half2*)&raw;
#pragma unroll
            for (int k = 0; k < 4; k++) {
                float2 f = __half22float2(h2p[k]);
                accv[2*k]   += f.x * a;
                accv[2*k+1] += f.y * a;
            }
        }
    }
    // combine the four quarter-warps' accumulators
#pragma unroll
    for (int k = 0; k < 8; k++) {
        accv[k] += __shfl_xor_sync(0xFFFFFFFFu, accv[k], 8);
        accv[k] += __shfl_xor_sync(0xFFFFFFFFu, accv[k], 16);
    }
    // denom partials live in lanes 0..3
    den += __shfl_xor_sync(0xFFFFFFFFu, den, 1);
    den += __shfl_xor_sync(0xFFFFFFFFu, den, 2);
    den  = __shfl_sync(0xFFFFFFFFu, den, 0);
    const float inv = 1.f / (den + 1e-16f);
    float v[8];
    {
        const float4 b0 = ((const float4*)b2)[ql * 2];
        const float4 b1v = ((const float4*)b2)[ql * 2 + 1];
        v[0] = accv[0]*inv + b0.x; v[1] = accv[1]*inv + b0.y;
        v[2] = accv[2]*inv + b0.z; v[3] = accv[3]*inv + b0.w;
        v[4] = accv[4]*inv + b1v.x; v[5] = accv[5]*inv + b1v.y;
        v[6] = accv[6]*inv + b1v.z; v[7] = accv[7]*inv + b1v.w;
    }
    // log_softmax over the 64 row values (8 lanes x 8 values, groups identical)
    float mx = v[0];
#pragma unroll
    for (int k = 1; k < 8; k++) mx = fmaxf(mx, v[k]);
#pragma unroll
    for (int o = 1; o < 8; o <<= 1)
        mx = fmaxf(mx, __shfl_xor_sync(0xFFFFFFFFu, mx, o));
    float s = 0.f;
#pragma unroll
    for (int k = 0; k < 8; k++) s += expf(v[k] - mx);
#pragma unroll
    for (int o = 1; o < 8; o <<= 1)
        s += __shfl_xor_sync(0xFFFFFFFFu, s, o);
    const float lse = logf(s) + mx;
    if (grp == 0) {
        float4 o0 = make_float4(v[0]-lse, v[1]-lse, v[2]-lse, v[3]-lse);
        float4 o1 = make_float4(v[4]-lse, v[5]-lse, v[6]-lse, v[7]-lse);
        ((float4*)out)[n * 16 + ql * 2]     = o0;
        ((float4*)out)[n * 16 + ql * 2 + 1] = o1;
    }
}

extern "C" void kernel_launch(void* const* d_in, const int* in_sizes, int n_in,
                              void* d_out, int out_size) {
    const float* x   = (const float*)d_in[0];
    const void*  ei  = d_in[1];                 // int32 or int64, probed inline
    const float* W1  = (const float*)d_in[2];
    const float* as1 = (const float*)d_in[3];
    const float* ad1 = (const float*)d_in[4];
    const float* b1  = (const float*)d_in[5];
    const float* W2  = (const float*)d_in[6];
    const float* as2 = (const float*)d_in[7];
    const float* ad2 = (const float*)d_in[8];
    const float* b2  = (const float*)d_in[9];
    float* out = (float*)d_out;

    const int warp_blocks = (N_NODES * 32 + 255) / 256;   // 6250

    fat1_k<<<GEMM_BLOCKS + DEC_BLOCKS, 256>>>(x, W1, as1, ad1, ei);  // GEMM1+alpha1 ∥ hist
    scan_k<<<SBLK, 512>>>();                                          // lookback scan
    scatter_k<<<(ET + 511) / 512, 512>>>(ei);
    agg1_k<<<warp_blocks, 256>>>(b1);
    gemm2_k<<<GEMM_BLOCKS, 256>>>(W2, as2, ad2);                      // GEMM2+alpha2
    agg2_k<<<warp_blocks, 256>>>(out, b2);
}